// round 1
// baseline (speedup 1.0000x reference)
#include <cuda_runtime.h>

#define BB 32
#define SS 512
#define RR 49
#define HH 768
#define NCB 6   // 768 / 128 column-blocks in the fused GEMM

// ---------------- scratch (device globals; no allocation allowed) ----------------
__device__ float g_ksc_part[NCB * BB * SS];   // partial tanh-dot sums, [colblk][row]
__device__ float g_isc_part[NCB * BB * RR];
__device__ __align__(16) float g_vft[HH];     // ft_w @ fg_w[:H]
__device__ __align__(16) float g_vfm[HH];     // fm_w @ fg_w[H:]
__device__ float g_fmc;                       // fm_b . fg_w[H:]
__device__ float g_fmsc[BB];                  // mm.v_fm + fmc + fg_b   (per batch)
__device__ __align__(16) float g_frout[BB * HH]; // tanh(mm @ fr_w + fr_b)

// ---------------- block reduce helpers ----------------
__device__ __forceinline__ float bsum(float v, float* sm) {
    int tid = threadIdx.x;
    sm[tid] = v; __syncthreads();
    for (int s = blockDim.x >> 1; s > 0; s >>= 1) {
        if (tid < s) sm[tid] += sm[tid + s];
        __syncthreads();
    }
    float r = sm[0]; __syncthreads();
    return r;
}

__device__ __forceinline__ float bmax(float v, float* sm) {
    int tid = threadIdx.x;
    sm[tid] = v; __syncthreads();
    for (int s = blockDim.x >> 1; s > 0; s >>= 1) {
        if (tid < s) sm[tid] = fmaxf(sm[tid], sm[tid + s]);
        __syncthreads();
    }
    float r = sm[0]; __syncthreads();
    return r;
}

// ---------------- prep: rank-1 collapses of ft/fm through fg_w ----------------
__global__ void prep_kernel(const float* __restrict__ ftw, const float* __restrict__ fmw,
                            const float* __restrict__ fmb, const float* __restrict__ fgw) {
    __shared__ float red[128];
    const int k = blockIdx.x, tid = threadIdx.x;
    float s1 = 0.f, s2 = 0.f, s3 = 0.f;
    for (int h = tid; h < HH; h += 128) {
        float g1 = fgw[h], g2 = fgw[HH + h];
        s1 += ftw[k * HH + h] * g1;
        s2 += fmw[k * HH + h] * g2;
        if (k == 0) s3 += fmb[h] * g2;
    }
    float t1 = bsum(s1, red);
    float t2 = bsum(s2, red);
    if (tid == 0) { g_vft[k] = t1; g_vfm[k] = t2; }
    if (k == 0) {
        float t3 = bsum(s3, red);
        if (tid == 0) g_fmc = t3;
    }
}

// ---------------- fused GEMM + tanh + dot-reduce ----------------
// out_sc[row] += sum_h tanh( (X @ W)[row, h] ) * av[h]  over this block's 128 cols.
// which: 0 -> g_isc_part, 1 -> g_ksc_part
__global__ __launch_bounds__(256, 2)
void gemm_tanh_dot(const float* __restrict__ X, const float* __restrict__ W,
                   const float* __restrict__ av, int nrows, int which) {
    __shared__ __align__(16) float As[16][132];
    __shared__ __align__(16) float Bs[16][128];
    float* outPart = which ? g_ksc_part : g_isc_part;

    const int tid = threadIdx.x;
    const int rowBase = blockIdx.x * 128;
    const int colBase = blockIdx.y * 128;
    const int ty = tid >> 4, tx = tid & 15;

    float acc[8][8];
#pragma unroll
    for (int i = 0; i < 8; i++)
#pragma unroll
        for (int j = 0; j < 8; j++) acc[i][j] = 0.f;

    for (int kt = 0; kt < HH; kt += 16) {
        // A tile: 128 rows x 16 k (transposed into smem)
#pragma unroll
        for (int i = 0; i < 2; i++) {
            int idx = tid + i * 256;
            int m = idx >> 2;
            int kg = (idx & 3) << 2;
            int gr = rowBase + m;
            float4 v = make_float4(0.f, 0.f, 0.f, 0.f);
            if (gr < nrows) v = *(const float4*)(X + gr * HH + kt + kg);
            As[kg + 0][m] = v.x; As[kg + 1][m] = v.y;
            As[kg + 2][m] = v.z; As[kg + 3][m] = v.w;
        }
        // B tile: 16 k x 128 n
#pragma unroll
        for (int i = 0; i < 2; i++) {
            int idx = tid + i * 256;
            int kk = idx >> 5;
            int ng = (idx & 31) << 2;
            *(float4*)&Bs[kk][ng] = *(const float4*)(W + (kt + kk) * HH + colBase + ng);
        }
        __syncthreads();
#pragma unroll
        for (int k = 0; k < 16; k++) {
            float a[8], b[8];
            *(float4*)&a[0] = *(const float4*)&As[k][ty * 8];
            *(float4*)&a[4] = *(const float4*)&As[k][ty * 8 + 4];
            *(float4*)&b[0] = *(const float4*)&Bs[k][tx * 8];
            *(float4*)&b[4] = *(const float4*)&Bs[k][tx * 8 + 4];
#pragma unroll
            for (int i = 0; i < 8; i++)
#pragma unroll
                for (int j = 0; j < 8; j++) acc[i][j] = fmaf(a[i], b[j], acc[i][j]);
        }
        __syncthreads();
    }

    float avv[8];
#pragma unroll
    for (int j = 0; j < 8; j++) avv[j] = av[colBase + tx * 8 + j];

#pragma unroll
    for (int i = 0; i < 8; i++) {
        float t = 0.f;
#pragma unroll
        for (int j = 0; j < 8; j++) t += tanhf(acc[i][j]) * avv[j];
#pragma unroll
        for (int off = 1; off < 16; off <<= 1) t += __shfl_xor_sync(0xffffffffu, t, off);
        if (tx == 0) {
            int r = rowBase + ty * 8 + i;
            if (r < nrows) outPart[blockIdx.y * nrows + r] = t;
        }
    }
}

// ---------------- per-batch fusion: softmaxes, attended vectors, gates, fr ----------------
__global__ void batch_kernel(const float* __restrict__ text, const float* __restrict__ img,
                             const float* __restrict__ giw, const float* __restrict__ gib,
                             const float* __restrict__ gtw, const float* __restrict__ gtb,
                             const float* __restrict__ ggw, const float* __restrict__ ggb,
                             const float* __restrict__ frw, const float* __restrict__ frb,
                             const float* __restrict__ fgb) {
    __shared__ float red[256];
    __shared__ float wimg[RR];
    __shared__ float wtxt[SS];
    __shared__ __align__(16) float attI[HH];
    __shared__ __align__(16) float attT[HH];
    __shared__ float nI[HH];
    __shared__ float nT[HH];
    __shared__ __align__(16) float mm[HH];
    const int b = blockIdx.x, tid = threadIdx.x;

    // --- visual softmax over R (t_sc + a1_b cancel under shift-invariance) ---
    float s0 = -1e30f;
    if (tid < RR) {
        float s = 0.f;
#pragma unroll
        for (int c = 0; c < NCB; c++) s += g_isc_part[c * (BB * RR) + b * RR + tid];
        wimg[tid] = s; s0 = s;
    }
    float mx = bmax(s0, red);
    float ex = 0.f;
    if (tid < RR) ex = expf(wimg[tid] - mx);
    float tot = bsum(ex, red);
    if (tid < RR) wimg[tid] = ex / tot;
    __syncthreads();

    // --- att_img[h] = sum_r w_img[r] * img[b,r,h] ---
    if (tid < 192) {
        float4 a = make_float4(0.f, 0.f, 0.f, 0.f);
        const float4* ip = (const float4*)(img + b * RR * HH) + tid;
        for (int r = 0; r < RR; r++) {
            float w = wimg[r];
            float4 v = ip[r * (HH / 4)];
            a.x += w * v.x; a.y += w * v.y; a.z += w * v.z; a.w += w * v.w;
        }
        *((float4*)attI + tid) = a;
    }

    // --- textual softmax over S (q_sc + a2_b cancel) ---
    float mx2 = -1e30f;
    for (int j = tid; j < SS; j += 256) {
        float s = 0.f;
#pragma unroll
        for (int c = 0; c < NCB; c++) s += g_ksc_part[c * (BB * SS) + b * SS + j];
        wtxt[j] = s; mx2 = fmaxf(mx2, s);
    }
    mx2 = bmax(mx2, red);
    float es = 0.f;
    for (int j = tid; j < SS; j += 256) { float e = expf(wtxt[j] - mx2); wtxt[j] = e; es += e; }
    tot = bsum(es, red);
    float inv = 1.f / tot;
    for (int j = tid; j < SS; j += 256) wtxt[j] *= inv;
    __syncthreads();

    // --- att_text[h] = sum_j w_txt[j] * text[b,j,h] ---
    if (tid < 192) {
        float4 a = make_float4(0.f, 0.f, 0.f, 0.f);
        const float4* tp = (const float4*)(text + b * SS * HH) + tid;
        for (int j = 0; j < SS; j++) {
            float w = wtxt[j];
            float4 v = tp[j * (HH / 4)];
            a.x += w * v.x; a.y += w * v.y; a.z += w * v.z; a.w += w * v.w;
        }
        *((float4*)attT + tid) = a;
    }
    __syncthreads();

    // --- new_img = tanh(attI @ gi_w + gi_b), new_txt = tanh(attT @ gt_w + gt_b) ---
    if (tid < 192) {
        float4 ai = make_float4(0.f, 0.f, 0.f, 0.f);
        float4 at = make_float4(0.f, 0.f, 0.f, 0.f);
        for (int k = 0; k < HH; k++) {
            float xi = attI[k], xt = attT[k];
            float4 wi = *(const float4*)(giw + k * HH + tid * 4);
            float4 wt = *(const float4*)(gtw + k * HH + tid * 4);
            ai.x += xi * wi.x; ai.y += xi * wi.y; ai.z += xi * wi.z; ai.w += xi * wi.w;
            at.x += xt * wt.x; at.y += xt * wt.y; at.z += xt * wt.z; at.w += xt * wt.w;
        }
        int h = tid * 4;
        nI[h + 0] = tanhf(ai.x + gib[h + 0]);
        nI[h + 1] = tanhf(ai.y + gib[h + 1]);
        nI[h + 2] = tanhf(ai.z + gib[h + 2]);
        nI[h + 3] = tanhf(ai.w + gib[h + 3]);
        nT[h + 0] = tanhf(at.x + gtb[h + 0]);
        nT[h + 1] = tanhf(at.y + gtb[h + 1]);
        nT[h + 2] = tanhf(at.z + gtb[h + 2]);
        nT[h + 3] = tanhf(at.w + gtb[h + 3]);
    }
    __syncthreads();

    // --- GMF gate (scalar per batch, since nI/nT are s-independent) ---
    float gp = 0.f;
    for (int h = tid; h < HH; h += 256) gp += nI[h] * ggw[h] + nT[h] * ggw[HH + h];
    float gs = bsum(gp, red);
    float gate = 1.f / (1.f + expf(-(gs + ggb[0])));

    // --- multimodal + fm score (rank-1 collapsed) ---
    float fmp = 0.f;
    for (int h = tid; h < HH; h += 256) {
        float v = gate * nI[h] + (1.f - gate) * nT[h];
        mm[h] = v;
        fmp += v * g_vfm[h];
    }
    float fsum = bsum(fmp, red);      // also syncs: mm[] visible below
    if (tid == 0) g_fmsc[b] = fsum + g_fmc + fgb[0];

    // --- fr_out = tanh(mm @ fr_w + fr_b) ---
    if (tid < 192) {
        float4 a = make_float4(0.f, 0.f, 0.f, 0.f);
        for (int k = 0; k < HH; k++) {
            float x = mm[k];
            float4 w = *(const float4*)(frw + k * HH + tid * 4);
            a.x += x * w.x; a.y += x * w.y; a.z += x * w.z; a.w += x * w.w;
        }
        int h = tid * 4;
        g_frout[b * HH + h + 0] = tanhf(a.x + frb[h + 0]);
        g_frout[b * HH + h + 1] = tanhf(a.y + frb[h + 1]);
        g_frout[b * HH + h + 2] = tanhf(a.z + frb[h + 2]);
        g_frout[b * HH + h + 3] = tanhf(a.w + frb[h + 3]);
    }
}

// ---------------- output: fgate[b,s] * fr_out[b,:] ----------------
__global__ void out_kernel(const float* __restrict__ text, float* __restrict__ out) {
    __shared__ float red[256];
    const int row = blockIdx.x;
    const int b = row >> 9;          // row / 512
    const int tid = threadIdx.x;
    float p = 0.f;
    if (tid < 192) {
        float4 tv = *((const float4*)(text + row * HH) + tid);
        float4 vv = *((const float4*)g_vft + tid);
        p = tv.x * vv.x + tv.y * vv.y + tv.z * vv.z + tv.w * vv.w;
    }
    float s = bsum(p, red);
    float fg = 1.f / (1.f + expf(-(s + g_fmsc[b])));
    if (tid < 192) {
        float4 fr = *((const float4*)(g_frout + b * HH) + tid);
        float4 o;
        o.x = fg * fr.x; o.y = fg * fr.y; o.z = fg * fr.z; o.w = fg * fr.w;
        *((float4*)(out + row * HH) + tid) = o;
    }
}

// ---------------- launch ----------------
extern "C" void kernel_launch(void* const* d_in, const int* in_sizes, int n_in,
                              void* d_out, int out_size) {
    const float* text = (const float*)d_in[0];
    const float* img  = (const float*)d_in[1];
    const float* i1w  = (const float*)d_in[4];
    const float* a1w  = (const float*)d_in[5];
    const float* t2w  = (const float*)d_in[7];
    const float* a2w  = (const float*)d_in[10];
    const float* gtw  = (const float*)d_in[12];
    const float* gtb  = (const float*)d_in[13];
    const float* giw  = (const float*)d_in[14];
    const float* gib  = (const float*)d_in[15];
    const float* ggw  = (const float*)d_in[16];
    const float* ggb  = (const float*)d_in[17];
    const float* ftw  = (const float*)d_in[18];
    const float* fmw  = (const float*)d_in[19];
    const float* fmb  = (const float*)d_in[20];
    const float* fgw  = (const float*)d_in[21];
    const float* fgb  = (const float*)d_in[22];
    const float* frw  = (const float*)d_in[23];
    const float* frb  = (const float*)d_in[24];
    float* out = (float*)d_out;

    // v_ft, v_fm, fm_const
    prep_kernel<<<HH, 128>>>(ftw, fmw, fmb, fgw);

    // i_sc partials: (1568,768) @ (768,768), fused tanh-dot with a1_w[H:]
    {
        dim3 g((BB * RR + 127) / 128, NCB);
        gemm_tanh_dot<<<g, 256>>>(img, i1w, a1w + HH, BB * RR, 0);
    }
    // k_sc partials: (16384,768) @ (768,768), fused tanh-dot with a2_w[H:]
    {
        dim3 g((BB * SS) / 128, NCB);
        gemm_tanh_dot<<<g, 256>>>(text, t2w, a2w + HH, BB * SS, 1);
    }

    // per-batch: softmaxes, att vectors, gi/gt/gg/fm/fr fusion
    batch_kernel<<<BB, 256>>>(text, img, giw, gib, gtw, gtb, ggw, ggb, frw, frb, fgb);

    // output: fgate(text . v_ft + fmsc) * fr_out
    out_kernel<<<BB * SS, 256>>>(text, out);
}

// round 3
// speedup vs baseline: 1.5151x; 1.5151x over previous
#include <cuda_runtime.h>

#define BB 32
#define SS 512
#define RR 49
#define HH 768
#define NCB 6   // 768 / 128 column-blocks in the fused GEMM

// ---------------- scratch (device globals; no allocation allowed) ----------------
__device__ float g_ksc_part[NCB * BB * SS];   // partial tanh-dot sums, [colblk][row]
__device__ float g_isc_part[NCB * BB * RR];
__device__ __align__(16) float g_vft[HH];     // ft_w @ fg_w[:H]
__device__ __align__(16) float g_vfm[HH];     // fm_w @ fg_w[H:]
__device__ float g_fmc;                       // fm_b . fg_w[H:]
__device__ float g_fmsc[BB];                  // mm.v_fm + fmc + fg_b   (per batch)
__device__ __align__(16) float g_frout[BB * HH]; // tanh(mm @ fr_w + fr_b)
__device__ float g_wimg[BB * RR];             // normalized visual softmax weights
__device__ float g_wtxt[BB * SS];             // normalized textual softmax weights
__device__ __align__(16) float g_attI[BB * HH];
__device__ __align__(16) float g_attT[BB * HH];
__device__ __align__(16) float g_nI[BB * HH];
__device__ __align__(16) float g_nT[BB * HH];
__device__ __align__(16) float g_mm[BB * HH];

// ---------------- block reduce helpers ----------------
__device__ __forceinline__ float bsum(float v, float* sm) {
    int tid = threadIdx.x;
    sm[tid] = v; __syncthreads();
    for (int s = blockDim.x >> 1; s > 0; s >>= 1) {
        if (tid < s) sm[tid] += sm[tid + s];
        __syncthreads();
    }
    float r = sm[0]; __syncthreads();
    return r;
}

__device__ __forceinline__ float bmax(float v, float* sm) {
    int tid = threadIdx.x;
    sm[tid] = v; __syncthreads();
    for (int s = blockDim.x >> 1; s > 0; s >>= 1) {
        if (tid < s) sm[tid] = fmaxf(sm[tid], sm[tid + s]);
        __syncthreads();
    }
    float r = sm[0]; __syncthreads();
    return r;
}

// ---------------- prep: rank-1 collapses of ft/fm through fg_w ----------------
__global__ void prep_kernel(const float* __restrict__ ftw, const float* __restrict__ fmw,
                            const float* __restrict__ fmb, const float* __restrict__ fgw) {
    __shared__ float red[128];
    const int k = blockIdx.x, tid = threadIdx.x;
    float s1 = 0.f, s2 = 0.f, s3 = 0.f;
    for (int h = tid; h < HH; h += 128) {
        float g1 = fgw[h], g2 = fgw[HH + h];
        s1 += ftw[k * HH + h] * g1;
        s2 += fmw[k * HH + h] * g2;
        if (k == 0) s3 += fmb[h] * g2;
    }
    float t1 = bsum(s1, red);
    float t2 = bsum(s2, red);
    if (tid == 0) { g_vft[k] = t1; g_vfm[k] = t2; }
    if (k == 0) {
        float t3 = bsum(s3, red);
        if (tid == 0) g_fmc = t3;
    }
}

// ---------------- fused GEMM + tanh + dot-reduce ----------------
__global__ __launch_bounds__(256, 2)
void gemm_tanh_dot(const float* __restrict__ X, const float* __restrict__ W,
                   const float* __restrict__ av, int nrows, int which) {
    __shared__ __align__(16) float As[16][132];
    __shared__ __align__(16) float Bs[16][128];
    float* outPart = which ? g_ksc_part : g_isc_part;

    const int tid = threadIdx.x;
    const int rowBase = blockIdx.x * 128;
    const int colBase = blockIdx.y * 128;
    const int ty = tid >> 4, tx = tid & 15;

    float acc[8][8];
#pragma unroll
    for (int i = 0; i < 8; i++)
#pragma unroll
        for (int j = 0; j < 8; j++) acc[i][j] = 0.f;

    for (int kt = 0; kt < HH; kt += 16) {
#pragma unroll
        for (int i = 0; i < 2; i++) {
            int idx = tid + i * 256;
            int m = idx >> 2;
            int kg = (idx & 3) << 2;
            int gr = rowBase + m;
            float4 v = make_float4(0.f, 0.f, 0.f, 0.f);
            if (gr < nrows) v = *(const float4*)(X + gr * HH + kt + kg);
            As[kg + 0][m] = v.x; As[kg + 1][m] = v.y;
            As[kg + 2][m] = v.z; As[kg + 3][m] = v.w;
        }
#pragma unroll
        for (int i = 0; i < 2; i++) {
            int idx = tid + i * 256;
            int kk = idx >> 5;
            int ng = (idx & 31) << 2;
            *(float4*)&Bs[kk][ng] = *(const float4*)(W + (kt + kk) * HH + colBase + ng);
        }
        __syncthreads();
#pragma unroll
        for (int k = 0; k < 16; k++) {
            float4 a0 = *(const float4*)&As[k][ty * 8];
            float4 a1 = *(const float4*)&As[k][ty * 8 + 4];
            float4 b0 = *(const float4*)&Bs[k][tx * 8];
            float4 b1 = *(const float4*)&Bs[k][tx * 8 + 4];
            float a[8] = {a0.x, a0.y, a0.z, a0.w, a1.x, a1.y, a1.z, a1.w};
            float b[8] = {b0.x, b0.y, b0.z, b0.w, b1.x, b1.y, b1.z, b1.w};
#pragma unroll
            for (int i = 0; i < 8; i++)
#pragma unroll
                for (int j = 0; j < 8; j++) acc[i][j] = fmaf(a[i], b[j], acc[i][j]);
        }
        __syncthreads();
    }

    float avv[8];
#pragma unroll
    for (int j = 0; j < 8; j++) avv[j] = av[colBase + tx * 8 + j];

#pragma unroll
    for (int i = 0; i < 8; i++) {
        float t = 0.f;
#pragma unroll
        for (int j = 0; j < 8; j++) t += tanhf(acc[i][j]) * avv[j];
#pragma unroll
        for (int off = 1; off < 16; off <<= 1) t += __shfl_xor_sync(0xffffffffu, t, off);
        if (tx == 0) {
            int r = rowBase + ty * 8 + i;
            if (r < nrows) outPart[blockIdx.y * nrows + r] = t;
        }
    }
}

// ---------------- softmaxes: reduce partials, normalize, write weights ----------------
__global__ void softmax_kernel() {
    __shared__ float red[256];
    __shared__ float w[SS];
    const int b = blockIdx.x, tid = threadIdx.x;

    // visual over R
    float s0 = -1e30f;
    if (tid < RR) {
        float s = 0.f;
#pragma unroll
        for (int c = 0; c < NCB; c++) s += g_isc_part[c * (BB * RR) + b * RR + tid];
        w[tid] = s; s0 = s;
    }
    float mx = bmax(s0, red);
    float ex = 0.f;
    if (tid < RR) ex = expf(w[tid] - mx);
    float tot = bsum(ex, red);
    if (tid < RR) g_wimg[b * RR + tid] = ex / tot;

    // textual over S
    float mx2 = -1e30f;
    for (int j = tid; j < SS; j += 256) {
        float s = 0.f;
#pragma unroll
        for (int c = 0; c < NCB; c++) s += g_ksc_part[c * (BB * SS) + b * SS + j];
        w[j] = s; mx2 = fmaxf(mx2, s);
    }
    mx2 = bmax(mx2, red);
    float es = 0.f;
    for (int j = tid; j < SS; j += 256) { float e = expf(w[j] - mx2); w[j] = e; es += e; }
    tot = bsum(es, red);
    float inv = 1.f / tot;
    for (int j = tid; j < SS; j += 256) g_wtxt[b * SS + j] = w[j] * inv;
}

// ---------------- attended vectors: grid (B, HH/128), block 128 ----------------
__global__ __launch_bounds__(128)
void attend_kernel(const float* __restrict__ text, const float* __restrict__ img) {
    __shared__ float wt[SS];
    __shared__ float wi[RR];
    const int b = blockIdx.x, tid = threadIdx.x;
    const int h = blockIdx.y * 128 + tid;

    for (int j = tid; j < SS; j += 128) wt[j] = g_wtxt[b * SS + j];
    if (tid < RR) wi[tid] = g_wimg[b * RR + tid];
    __syncthreads();

    // att_text
    {
        const float* tp = text + b * SS * HH + h;
        float a0 = 0.f, a1 = 0.f, a2 = 0.f, a3 = 0.f;
#pragma unroll 4
        for (int j = 0; j < SS; j += 4) {
            a0 += wt[j + 0] * tp[(j + 0) * HH];
            a1 += wt[j + 1] * tp[(j + 1) * HH];
            a2 += wt[j + 2] * tp[(j + 2) * HH];
            a3 += wt[j + 3] * tp[(j + 3) * HH];
        }
        g_attT[b * HH + h] = (a0 + a1) + (a2 + a3);
    }
    // att_img
    {
        const float* ip = img + b * RR * HH + h;
        float a = 0.f;
#pragma unroll
        for (int r = 0; r < RR; r++) a += wi[r] * ip[r * HH];
        g_attI[b * HH + h] = a;
    }
}

// ---------------- small GEMM: C[32,768] = tanh(A[32,768] @ W + bias) ----------------
// grid.x = 6 column-blocks of 128; grid.y selects (A,W,bias,C) set 0 or 1.
__global__ __launch_bounds__(256)
void small_gemm_tanh(const float* __restrict__ A0, const float* __restrict__ W0,
                     const float* __restrict__ b0, float* __restrict__ C0,
                     const float* __restrict__ A1, const float* __restrict__ W1,
                     const float* __restrict__ b1, float* __restrict__ C1) {
    const float* A = blockIdx.y ? A1 : A0;
    const float* W = blockIdx.y ? W1 : W0;
    const float* bias = blockIdx.y ? b1 : b0;
    float* C = blockIdx.y ? C1 : C0;

    // 36-float row stride = 144 bytes -> every row 16B-aligned for float4 reads
    __shared__ __align__(16) float As[32][36];   // [k][row]
    __shared__ __align__(16) float Ws[32][128];  // [k][col]
    const int tid = threadIdx.x;
    const int colBase = blockIdx.x * 128;
    const int tx = tid & 31;          // col group (4 cols each)
    const int ty = tid >> 5;          // row group (4 rows each), 8 groups

    float acc[4][4];
#pragma unroll
    for (int i = 0; i < 4; i++)
#pragma unroll
        for (int j = 0; j < 4; j++) acc[i][j] = 0.f;

    for (int kt = 0; kt < HH; kt += 32) {
        // A tile: 32 rows x 32 k -> transposed
        {
            int r = tid >> 3;            // 0..31
            int kg = (tid & 7) << 2;     // 0..28
            float4 v = *(const float4*)(A + r * HH + kt + kg);
            As[kg + 0][r] = v.x; As[kg + 1][r] = v.y;
            As[kg + 2][r] = v.z; As[kg + 3][r] = v.w;
        }
        // W tile: 32 k x 128 cols
#pragma unroll
        for (int i = 0; i < 4; i++) {
            int idx = tid + i * 256;
            int kk = idx >> 5;
            int ng = (idx & 31) << 2;
            *(float4*)&Ws[kk][ng] = *(const float4*)(W + (kt + kk) * HH + colBase + ng);
        }
        __syncthreads();
#pragma unroll
        for (int k = 0; k < 32; k++) {
            float4 av4 = *(const float4*)&As[k][ty * 4];
            float4 w = *(const float4*)&Ws[k][tx * 4];
            float a[4] = {av4.x, av4.y, av4.z, av4.w};
#pragma unroll
            for (int i = 0; i < 4; i++) {
                acc[i][0] = fmaf(a[i], w.x, acc[i][0]);
                acc[i][1] = fmaf(a[i], w.y, acc[i][1]);
                acc[i][2] = fmaf(a[i], w.z, acc[i][2]);
                acc[i][3] = fmaf(a[i], w.w, acc[i][3]);
            }
        }
        __syncthreads();
    }

    int col = colBase + tx * 4;
    float4 bv = *(const float4*)(bias + col);
#pragma unroll
    for (int i = 0; i < 4; i++) {
        int row = ty * 4 + i;
        float4 o;
        o.x = tanhf(acc[i][0] + bv.x);
        o.y = tanhf(acc[i][1] + bv.y);
        o.z = tanhf(acc[i][2] + bv.z);
        o.w = tanhf(acc[i][3] + bv.w);
        *(float4*)(C + row * HH + col) = o;
    }
}

// ---------------- gate + multimodal + fm score ----------------
__global__ void gate_mm_kernel(const float* __restrict__ ggw, const float* __restrict__ ggb,
                               const float* __restrict__ fgb) {
    __shared__ float red[256];
    const int b = blockIdx.x, tid = threadIdx.x;

    float gp = 0.f;
    for (int h = tid; h < HH; h += 256)
        gp += g_nI[b * HH + h] * ggw[h] + g_nT[b * HH + h] * ggw[HH + h];
    float gs = bsum(gp, red);
    float gate = 1.f / (1.f + expf(-(gs + ggb[0])));

    float fmp = 0.f;
    for (int h = tid; h < HH; h += 256) {
        float v = gate * g_nI[b * HH + h] + (1.f - gate) * g_nT[b * HH + h];
        g_mm[b * HH + h] = v;
        fmp += v * g_vfm[h];
    }
    float fsum = bsum(fmp, red);
    if (tid == 0) g_fmsc[b] = fsum + g_fmc + fgb[0];
}

// ---------------- output: warp per row ----------------
__global__ __launch_bounds__(256)
void out_kernel(const float* __restrict__ text, float* __restrict__ out) {
    const int warp = threadIdx.x >> 5;
    const int lane = threadIdx.x & 31;
    const int row = blockIdx.x * 8 + warp;
    const int b = row >> 9;

    const float4* tv = (const float4*)(text + row * HH);
    const float4* vv = (const float4*)g_vft;
    float p = 0.f;
#pragma unroll
    for (int i = 0; i < 6; i++) {
        float4 t = tv[lane + i * 32];
        float4 v = vv[lane + i * 32];
        p += t.x * v.x + t.y * v.y + t.z * v.z + t.w * v.w;
    }
#pragma unroll
    for (int off = 16; off > 0; off >>= 1) p += __shfl_xor_sync(0xffffffffu, p, off);
    float fg = 1.f / (1.f + expf(-(p + g_fmsc[b])));

    const float4* fr = (const float4*)(g_frout + b * HH);
    float4* op = (float4*)(out + row * HH);
#pragma unroll
    for (int i = 0; i < 6; i++) {
        float4 f = fr[lane + i * 32];
        float4 o;
        o.x = fg * f.x; o.y = fg * f.y; o.z = fg * f.z; o.w = fg * f.w;
        op[lane + i * 32] = o;
    }
}

// ---------------- launch ----------------
extern "C" void kernel_launch(void* const* d_in, const int* in_sizes, int n_in,
                              void* d_out, int out_size) {
    const float* text = (const float*)d_in[0];
    const float* img  = (const float*)d_in[1];
    const float* i1w  = (const float*)d_in[4];
    const float* a1w  = (const float*)d_in[5];
    const float* t2w  = (const float*)d_in[7];
    const float* a2w  = (const float*)d_in[10];
    const float* gtw  = (const float*)d_in[12];
    const float* gtb  = (const float*)d_in[13];
    const float* giw  = (const float*)d_in[14];
    const float* gib  = (const float*)d_in[15];
    const float* ggw  = (const float*)d_in[16];
    const float* ggb  = (const float*)d_in[17];
    const float* ftw  = (const float*)d_in[18];
    const float* fmw  = (const float*)d_in[19];
    const float* fmb  = (const float*)d_in[20];
    const float* fgw  = (const float*)d_in[21];
    const float* fgb  = (const float*)d_in[22];
    const float* frw  = (const float*)d_in[23];
    const float* frb  = (const float*)d_in[24];
    float* out = (float*)d_out;

    float* attI; cudaGetSymbolAddress((void**)&attI, g_attI);
    float* attT; cudaGetSymbolAddress((void**)&attT, g_attT);
    float* nI;   cudaGetSymbolAddress((void**)&nI,   g_nI);
    float* nT;   cudaGetSymbolAddress((void**)&nT,   g_nT);
    float* mm;   cudaGetSymbolAddress((void**)&mm,   g_mm);
    float* frout;cudaGetSymbolAddress((void**)&frout,g_frout);

    prep_kernel<<<HH, 128>>>(ftw, fmw, fmb, fgw);

    {
        dim3 g((BB * RR + 127) / 128, NCB);
        gemm_tanh_dot<<<g, 256>>>(img, i1w, a1w + HH, BB * RR, 0);
    }
    {
        dim3 g((BB * SS) / 128, NCB);
        gemm_tanh_dot<<<g, 256>>>(text, t2w, a2w + HH, BB * SS, 1);
    }

    softmax_kernel<<<BB, 256>>>();

    {
        dim3 g(BB, NCB);
        attend_kernel<<<g, 128>>>(text, img);
    }

    // nI = tanh(attI @ gi_w + gi_b); nT = tanh(attT @ gt_w + gt_b)
    {
        dim3 g(NCB, 2);
        small_gemm_tanh<<<g, 256>>>(attI, giw, gib, nI, attT, gtw, gtb, nT);
    }

    gate_mm_kernel<<<BB, 256>>>(ggw, ggb, fgb);

    // fr_out = tanh(mm @ fr_w + fr_b)
    {
        dim3 g(NCB, 1);
        small_gemm_tanh<<<g, 256>>>(mm, frw, frb, frout, mm, frw, frb, frout);
    }

    out_kernel<<<(BB * SS) / 8, 256>>>(text, out);
}

// round 5
// speedup vs baseline: 2.9361x; 1.9379x over previous
#include <cuda_runtime.h>
#include <cuda_bf16.h>
#include <stdint.h>

#define BB 32
#define SS 512
#define RR 49
#define HH 768
#define NCB 6              // 128-col blocks for attend/small_gemm
#define NPART 24           // 32-col partial groups for the tensor GEMM
#define MROWS_T (BB*SS)    // 16384
#define NROWS_I (BB*RR)    // 1568
#define MROWS_I 1664       // padded to 13*128

// ================= PTX helpers (sm_103-safe: ldmatrix / mma.sync / cp.async) =======
__device__ __forceinline__ uint32_t smem_u32(const void* p) {
    uint32_t a;
    asm("{ .reg .u64 t; cvta.to.shared.u64 t, %1; cvt.u32.u64 %0, t; }" : "=r"(a) : "l"(p));
    return a;
}
#define SMEM_SWIZZLE_128B(x) ((x) ^ (((x) >> 3) & 0x70))

__device__ __forceinline__ void cpa16(uint32_t s, const void* g) {
    asm volatile("cp.async.cg.shared.global [%0], [%1], 16;" :: "r"(s), "l"(g));
}
__device__ __forceinline__ void ldmx4(uint32_t* r, uint32_t addr) {
    asm volatile("ldmatrix.sync.aligned.m8n8.x4.shared.b16 {%0,%1,%2,%3}, [%4];"
                 : "=r"(r[0]), "=r"(r[1]), "=r"(r[2]), "=r"(r[3]) : "r"(addr));
}
__device__ __forceinline__ void mma16816(float* c, const uint32_t* a, uint32_t b0, uint32_t b1) {
    asm volatile(
        "mma.sync.aligned.m16n8k16.row.col.f32.bf16.bf16.f32 "
        "{%0,%1,%2,%3}, {%4,%5,%6,%7}, {%8,%9}, {%0,%1,%2,%3};"
        : "+f"(c[0]), "+f"(c[1]), "+f"(c[2]), "+f"(c[3])
        : "r"(a[0]), "r"(a[1]), "r"(a[2]), "r"(a[3]), "r"(b0), "r"(b1));
}
__device__ __forceinline__ float fast_tanh(float x) {
    const float e = __expf(2.f * x);
    return 1.f - __fdividef(2.f, e + 1.f);
}

// ================= scratch (device globals) =================
__device__ float g_ksc_part[NPART * MROWS_T];
__device__ float g_isc_part[NPART * NROWS_I];
__device__ __align__(16) float g_vft[HH];
__device__ __align__(16) float g_vfm[HH];
__device__ float g_fmc;
__device__ float g_fmsc[BB];
__device__ __align__(16) float g_frout[BB * HH];
__device__ float g_wimg[BB * RR];
__device__ float g_wtxt[BB * SS];
__device__ __align__(16) float g_attI[BB * HH];
__device__ __align__(16) float g_attT[BB * HH];
__device__ __align__(16) float g_nI[BB * HH];
__device__ __align__(16) float g_nT[BB * HH];
__device__ __align__(16) float g_mm[BB * HH];
// bf16 split inputs/weights
__device__ __align__(16) __nv_bfloat16 g_tHi[MROWS_T * HH];
__device__ __align__(16) __nv_bfloat16 g_tLo[MROWS_T * HH];
__device__ __align__(16) __nv_bfloat16 g_iHi[MROWS_I * HH];   // pad rows stay zero
__device__ __align__(16) __nv_bfloat16 g_iLo[MROWS_I * HH];
__device__ __align__(16) __nv_bfloat16 g_w2Hi[HH * HH];       // t2_w transposed [n][k]
__device__ __align__(16) __nv_bfloat16 g_w2Lo[HH * HH];
__device__ __align__(16) __nv_bfloat16 g_w1Hi[HH * HH];       // i1_w transposed [n][k]
__device__ __align__(16) __nv_bfloat16 g_w1Lo[HH * HH];

// ================= block reduce helpers =================
__device__ __forceinline__ float bsum(float v, float* sm) {
    int tid = threadIdx.x;
    sm[tid] = v; __syncthreads();
    for (int s = blockDim.x >> 1; s > 0; s >>= 1) {
        if (tid < s) sm[tid] += sm[tid + s];
        __syncthreads();
    }
    float r = sm[0]; __syncthreads();
    return r;
}
__device__ __forceinline__ float bmax(float v, float* sm) {
    int tid = threadIdx.x;
    sm[tid] = v; __syncthreads();
    for (int s = blockDim.x >> 1; s > 0; s >>= 1) {
        if (tid < s) sm[tid] = fmaxf(sm[tid], sm[tid + s]);
        __syncthreads();
    }
    float r = sm[0]; __syncthreads();
    return r;
}

// ================= input split kernels =================
__global__ __launch_bounds__(256)
void split4(const float* __restrict__ x, __nv_bfloat16* __restrict__ hi,
            __nv_bfloat16* __restrict__ lo, int n4) {
    int i = blockIdx.x * 256 + threadIdx.x;
    if (i >= n4) return;
    float4 v = ((const float4*)x)[i];
    float f[4] = {v.x, v.y, v.z, v.w};
    union P { __nv_bfloat16 b[4]; uint2 u; } H, L;
#pragma unroll
    for (int j = 0; j < 4; j++) {
        H.b[j] = __float2bfloat16(f[j]);
        L.b[j] = __float2bfloat16(f[j] - __bfloat162float(H.b[j]));
    }
    ((uint2*)hi)[i] = H.u;
    ((uint2*)lo)[i] = L.u;
}

// transpose + split weights: Ht[n][k] = bf16(W[k][n]); grid (24,24,2), block (32,8)
__global__ void tsplit(const float* __restrict__ W0, const float* __restrict__ W1) {
    __shared__ float t[32][33];
    const float* W = blockIdx.z ? W1 : W0;
    __nv_bfloat16* Hi = blockIdx.z ? g_w1Hi : g_w2Hi;
    __nv_bfloat16* Lo = blockIdx.z ? g_w1Lo : g_w2Lo;
    const int kb = blockIdx.x * 32, nb = blockIdx.y * 32;
    const int tx = threadIdx.x, ty = threadIdx.y;
#pragma unroll
    for (int i = 0; i < 4; ++i)
        t[ty + 8 * i][tx] = W[(size_t)(kb + ty + 8 * i) * HH + nb + tx];
    __syncthreads();
#pragma unroll
    for (int i = 0; i < 4; ++i) {
        const float v = t[tx][ty + 8 * i];
        const __nv_bfloat16 h = __float2bfloat16(v);
        Hi[(size_t)(nb + ty + 8 * i) * HH + kb + tx] = h;
        Lo[(size_t)(nb + ty + 8 * i) * HH + kb + tx] =
            __float2bfloat16(v - __bfloat162float(h));
    }
}

// ================= prep: rank-1 collapses =================
__global__ void prep_kernel(const float* __restrict__ ftw, const float* __restrict__ fmw,
                            const float* __restrict__ fmb, const float* __restrict__ fgw) {
    __shared__ float red[128];
    const int k = blockIdx.x, tid = threadIdx.x;
    float s1 = 0.f, s2 = 0.f, s3 = 0.f;
    for (int h = tid; h < HH; h += 128) {
        float g1 = fgw[h], g2 = fgw[HH + h];
        s1 += ftw[k * HH + h] * g1;
        s2 += fmw[k * HH + h] * g2;
        if (k == 0) s3 += fmb[h] * g2;
    }
    float t1 = bsum(s1, red);
    float t2 = bsum(s2, red);
    if (tid == 0) { g_vft[k] = t1; g_vfm[k] = t2; }
    if (k == 0) {
        float t3 = bsum(s3, red);
        if (tid == 0) g_fmc = t3;
    }
}

// ================= mma.sync bf16 GEMM + tanh + dot epilogue =================
// C[128x128] per CTA; K = 3 passes x 768 = 36 chunks of 64.
// smem: buf0 {A 16K, B 16K}, buf1 {A 16K, B 16K} = 64 KB dynamic.
#define HMMA_SMEM (64 * 1024)
struct ChunkSrc { const __nv_bfloat16 *a, *b; int kt; };

__device__ __forceinline__ void issue_chunk(
    const __nv_bfloat16* __restrict__ Ap, const __nv_bfloat16* __restrict__ Bp,
    int kt, uint32_t abase, uint32_t bbase, int tid, int rowBase, int colBase) {
#pragma unroll
    for (int i = 0; i < 4; i++) {
        int u = tid + i * 256;                 // 1024 x 16B units
        const __nv_bfloat16* g = Ap + (size_t)(rowBase + (u >> 3)) * HH + kt + (u & 7) * 8;
        cpa16(abase + SMEM_SWIZZLE_128B((uint32_t)u * 16u), g);
    }
#pragma unroll
    for (int i = 0; i < 4; i++) {
        int u = tid + i * 256;
        const __nv_bfloat16* g = Bp + (size_t)(colBase + (u >> 3)) * HH + kt + (u & 7) * 8;
        cpa16(bbase + SMEM_SWIZZLE_128B((uint32_t)u * 16u), g);
    }
    asm volatile("cp.async.commit_group;");
}

__global__ __launch_bounds__(256, 2)
void hmma_tanh_dot(const __nv_bfloat16* __restrict__ AHi, const __nv_bfloat16* __restrict__ ALo,
                   const __nv_bfloat16* __restrict__ WHi, const __nv_bfloat16* __restrict__ WLo,
                   const float* __restrict__ av, float* __restrict__ outPart, int nrows) {
    extern __shared__ __align__(1024) char smem[];
    const uint32_t sb = smem_u32(smem);
    const int tid = threadIdx.x;
    const int wid = tid >> 5, lane = tid & 31;
    const int warpm = wid & 1, warpn = wid >> 1;   // 2 x 4 warp grid
    const int rowBase = blockIdx.x * 128;
    const int colBase = blockIdx.y * 128;

    float acc[4][4][4];
#pragma unroll
    for (int i = 0; i < 4; i++)
#pragma unroll
        for (int j = 0; j < 4; j++)
#pragma unroll
            for (int q = 0; q < 4; q++) acc[i][j][q] = 0.f;

    // chunk source for iteration it
    auto src = [&](int it, const __nv_bfloat16*& Ap, const __nv_bfloat16*& Bp, int& kt) {
        const int pass = it / 12;
        kt = (it % 12) * 64;
        Ap = (pass == 2) ? ALo : AHi;
        Bp = (pass == 1) ? WLo : WHi;
    };

    {
        const __nv_bfloat16 *Ap, *Bp; int kt;
        src(0, Ap, Bp, kt);
        issue_chunk(Ap, Bp, kt, sb, sb + 16384u, tid, rowBase, colBase);
    }

    for (int it = 0; it < 36; ++it) {
        if (it < 35) {
            const __nv_bfloat16 *Ap, *Bp; int kt;
            src(it + 1, Ap, Bp, kt);
            const uint32_t nb = sb + ((it + 1) & 1) * 32768u;
            issue_chunk(Ap, Bp, kt, nb, nb + 16384u, tid, rowBase, colBase);
            asm volatile("cp.async.wait_group 1;");
        } else {
            asm volatile("cp.async.wait_group 0;");
        }
        __syncthreads();

        const uint32_t abase = sb + (it & 1) * 32768u;
        const uint32_t bbase = abase + 16384u;
#pragma unroll
        for (int ks = 0; ks < 4; ++ks) {
            uint32_t bfrag[2][4];
#pragma unroll
            for (int g = 0; g < 2; ++g) {
                const int n = warpn * 32 + g * 16 + (lane & 7) + ((lane >> 4) << 3);
                const int kb = ks * 32 + ((lane >> 3) & 1) * 16;
                ldmx4(bfrag[g], bbase + SMEM_SWIZZLE_128B((uint32_t)(n * 128 + kb)));
            }
#pragma unroll
            for (int mt = 0; mt < 4; ++mt) {
                uint32_t a[4];
                const int r = warpm * 64 + mt * 16 + (lane & 15);
                const int kb = ks * 32 + ((lane >> 4) << 4);
                ldmx4(a, abase + SMEM_SWIZZLE_128B((uint32_t)(r * 128 + kb)));
#pragma unroll
                for (int nt = 0; nt < 4; ++nt)
                    mma16816(acc[mt][nt], a, bfrag[nt >> 1][(nt & 1) * 2],
                             bfrag[nt >> 1][(nt & 1) * 2 + 1]);
            }
        }
        __syncthreads();
    }

    // ---- epilogue: tanh * av, reduce over this warp's 32 cols, write row partials ----
    const float* avp = av + colBase + warpn * 32;
    float avv[4][2];
#pragma unroll
    for (int nt = 0; nt < 4; ++nt) {
        avv[nt][0] = avp[nt * 8 + (lane & 3) * 2];
        avv[nt][1] = avp[nt * 8 + (lane & 3) * 2 + 1];
    }
    const int gcol = blockIdx.y * 4 + warpn;
#pragma unroll
    for (int mt = 0; mt < 4; ++mt) {
        float s0 = 0.f, s1 = 0.f;
#pragma unroll
        for (int nt = 0; nt < 4; ++nt) {
            s0 += fast_tanh(acc[mt][nt][0]) * avv[nt][0] + fast_tanh(acc[mt][nt][1]) * avv[nt][1];
            s1 += fast_tanh(acc[mt][nt][2]) * avv[nt][0] + fast_tanh(acc[mt][nt][3]) * avv[nt][1];
        }
        s0 += __shfl_xor_sync(0xffffffffu, s0, 1);
        s0 += __shfl_xor_sync(0xffffffffu, s0, 2);
        s1 += __shfl_xor_sync(0xffffffffu, s1, 1);
        s1 += __shfl_xor_sync(0xffffffffu, s1, 2);
        if ((lane & 3) == 0) {
            const int r0 = rowBase + warpm * 64 + mt * 16 + (lane >> 2);
            if (r0 < nrows) outPart[gcol * nrows + r0] = s0;
            if (r0 + 8 < nrows) outPart[gcol * nrows + r0 + 8] = s1;
        }
    }
}

// ================= softmaxes =================
__global__ void softmax_kernel() {
    __shared__ float red[256];
    __shared__ float w[SS];
    const int b = blockIdx.x, tid = threadIdx.x;

    float s0 = -1e30f;
    if (tid < RR) {
        float s = 0.f;
#pragma unroll
        for (int c = 0; c < NPART; c++) s += g_isc_part[c * NROWS_I + b * RR + tid];
        w[tid] = s; s0 = s;
    }
    float mx = bmax(s0, red);
    float ex = 0.f;
    if (tid < RR) ex = expf(w[tid] - mx);
    float tot = bsum(ex, red);
    if (tid < RR) g_wimg[b * RR + tid] = ex / tot;

    float mx2 = -1e30f;
    for (int j = tid; j < SS; j += 256) {
        float s = 0.f;
#pragma unroll
        for (int c = 0; c < NPART; c++) s += g_ksc_part[c * MROWS_T + b * SS + j];
        w[j] = s; mx2 = fmaxf(mx2, s);
    }
    mx2 = bmax(mx2, red);
    float es = 0.f;
    for (int j = tid; j < SS; j += 256) { float e = expf(w[j] - mx2); w[j] = e; es += e; }
    tot = bsum(es, red);
    float inv = 1.f / tot;
    for (int j = tid; j < SS; j += 256) g_wtxt[b * SS + j] = w[j] * inv;
}

// ================= attended vectors =================
__global__ __launch_bounds__(128)
void attend_kernel(const float* __restrict__ text, const float* __restrict__ img) {
    __shared__ float wt[SS];
    __shared__ float wi[RR];
    const int b = blockIdx.x, tid = threadIdx.x;
    const int h = blockIdx.y * 128 + tid;

    for (int j = tid; j < SS; j += 128) wt[j] = g_wtxt[b * SS + j];
    if (tid < RR) wi[tid] = g_wimg[b * RR + tid];
    __syncthreads();

    {
        const float* tp = text + b * SS * HH + h;
        float a0 = 0.f, a1 = 0.f, a2 = 0.f, a3 = 0.f;
#pragma unroll 4
        for (int j = 0; j < SS; j += 4) {
            a0 += wt[j + 0] * tp[(j + 0) * HH];
            a1 += wt[j + 1] * tp[(j + 1) * HH];
            a2 += wt[j + 2] * tp[(j + 2) * HH];
            a3 += wt[j + 3] * tp[(j + 3) * HH];
        }
        g_attT[b * HH + h] = (a0 + a1) + (a2 + a3);
    }
    {
        const float* ip = img + b * RR * HH + h;
        float a = 0.f;
#pragma unroll
        for (int r = 0; r < RR; r++) a += wi[r] * ip[r * HH];
        g_attI[b * HH + h] = a;
    }
}

// ================= small GEMM: C[32,768] = tanh(A @ W + bias) =================
__global__ __launch_bounds__(256)
void small_gemm_tanh(const float* __restrict__ A0, const float* __restrict__ W0,
                     const float* __restrict__ b0, float* __restrict__ C0,
                     const float* __restrict__ A1, const float* __restrict__ W1,
                     const float* __restrict__ b1, float* __restrict__ C1) {
    const float* A = blockIdx.y ? A1 : A0;
    const float* W = blockIdx.y ? W1 : W0;
    const float* bias = blockIdx.y ? b1 : b0;
    float* C = blockIdx.y ? C1 : C0;

    __shared__ __align__(16) float As[32][36];
    __shared__ __align__(16) float Ws[32][128];
    const int tid = threadIdx.x;
    const int colBase = blockIdx.x * 128;
    const int tx = tid & 31;
    const int ty = tid >> 5;

    float acc[4][4];
#pragma unroll
    for (int i = 0; i < 4; i++)
#pragma unroll
        for (int j = 0; j < 4; j++) acc[i][j] = 0.f;

    for (int kt = 0; kt < HH; kt += 32) {
        {
            int r = tid >> 3;
            int kg = (tid & 7) << 2;
            float4 v = *(const float4*)(A + r * HH + kt + kg);
            As[kg + 0][r] = v.x; As[kg + 1][r] = v.y;
            As[kg + 2][r] = v.z; As[kg + 3][r] = v.w;
        }
#pragma unroll
        for (int i = 0; i < 4; i++) {
            int idx = tid + i * 256;
            int kk = idx >> 5;
            int ng = (idx & 31) << 2;
            *(float4*)&Ws[kk][ng] = *(const float4*)(W + (kt + kk) * HH + colBase + ng);
        }
        __syncthreads();
#pragma unroll
        for (int k = 0; k < 32; k++) {
            float4 av4 = *(const float4*)&As[k][ty * 4];
            float4 w = *(const float4*)&Ws[k][tx * 4];
            float a[4] = {av4.x, av4.y, av4.z, av4.w};
#pragma unroll
            for (int i = 0; i < 4; i++) {
                acc[i][0] = fmaf(a[i], w.x, acc[i][0]);
                acc[i][1] = fmaf(a[i], w.y, acc[i][1]);
                acc[i][2] = fmaf(a[i], w.z, acc[i][2]);
                acc[i][3] = fmaf(a[i], w.w, acc[i][3]);
            }
        }
        __syncthreads();
    }

    int col = colBase + tx * 4;
    float4 bv = *(const float4*)(bias + col);
#pragma unroll
    for (int i = 0; i < 4; i++) {
        int row = ty * 4 + i;
        float4 o;
        o.x = tanhf(acc[i][0] + bv.x);
        o.y = tanhf(acc[i][1] + bv.y);
        o.z = tanhf(acc[i][2] + bv.z);
        o.w = tanhf(acc[i][3] + bv.w);
        *(float4*)(C + row * HH + col) = o;
    }
}

// ================= gate + multimodal + fm score =================
__global__ void gate_mm_kernel(const float* __restrict__ ggw, const float* __restrict__ ggb,
                               const float* __restrict__ fgb) {
    __shared__ float red[256];
    const int b = blockIdx.x, tid = threadIdx.x;

    float gp = 0.f;
    for (int h = tid; h < HH; h += 256)
        gp += g_nI[b * HH + h] * ggw[h] + g_nT[b * HH + h] * ggw[HH + h];
    float gs = bsum(gp, red);
    float gate = 1.f / (1.f + expf(-(gs + ggb[0])));

    float fmp = 0.f;
    for (int h = tid; h < HH; h += 256) {
        float v = gate * g_nI[b * HH + h] + (1.f - gate) * g_nT[b * HH + h];
        g_mm[b * HH + h] = v;
        fmp += v * g_vfm[h];
    }
    float fsum = bsum(fmp, red);
    if (tid == 0) g_fmsc[b] = fsum + g_fmc + fgb[0];
}

// ================= output: warp per row =================
__global__ __launch_bounds__(256)
void out_kernel(const float* __restrict__ text, float* __restrict__ out) {
    const int warp = threadIdx.x >> 5;
    const int lane = threadIdx.x & 31;
    const int row = blockIdx.x * 8 + warp;
    const int b = row >> 9;

    const float4* tv = (const float4*)(text + row * HH);
    const float4* vv = (const float4*)g_vft;
    float p = 0.f;
#pragma unroll
    for (int i = 0; i < 6; i++) {
        float4 t = tv[lane + i * 32];
        float4 v = vv[lane + i * 32];
        p += t.x * v.x + t.y * v.y + t.z * v.z + t.w * v.w;
    }
#pragma unroll
    for (int off = 16; off > 0; off >>= 1) p += __shfl_xor_sync(0xffffffffu, p, off);
    float fg = 1.f / (1.f + expf(-(p + g_fmsc[b])));

    const float4* fr = (const float4*)(g_frout + b * HH);
    float4* op = (float4*)(out + row * HH);
#pragma unroll
    for (int i = 0; i < 6; i++) {
        float4 f = fr[lane + i * 32];
        float4 o;
        o.x = fg * f.x; o.y = fg * f.y; o.z = fg * f.z; o.w = fg * f.w;
        op[lane + i * 32] = o;
    }
}

// ================= launch =================
extern "C" void kernel_launch(void* const* d_in, const int* in_sizes, int n_in,
                              void* d_out, int out_size) {
    const float* text = (const float*)d_in[0];
    const float* img  = (const float*)d_in[1];
    const float* i1w  = (const float*)d_in[4];
    const float* a1w  = (const float*)d_in[5];
    const float* t2w  = (const float*)d_in[7];
    const float* a2w  = (const float*)d_in[10];
    const float* gtw  = (const float*)d_in[12];
    const float* gtb  = (const float*)d_in[13];
    const float* giw  = (const float*)d_in[14];
    const float* gib  = (const float*)d_in[15];
    const float* ggw  = (const float*)d_in[16];
    const float* ggb  = (const float*)d_in[17];
    const float* ftw  = (const float*)d_in[18];
    const float* fmw  = (const float*)d_in[19];
    const float* fmb  = (const float*)d_in[20];
    const float* fgw  = (const float*)d_in[21];
    const float* fgb  = (const float*)d_in[22];
    const float* frw  = (const float*)d_in[23];
    const float* frb  = (const float*)d_in[24];
    float* out = (float*)d_out;

    float* attI;  cudaGetSymbolAddress((void**)&attI,  g_attI);
    float* attT;  cudaGetSymbolAddress((void**)&attT,  g_attT);
    float* nI;    cudaGetSymbolAddress((void**)&nI,    g_nI);
    float* nT;    cudaGetSymbolAddress((void**)&nT,    g_nT);
    float* mm;    cudaGetSymbolAddress((void**)&mm,    g_mm);
    float* frout; cudaGetSymbolAddress((void**)&frout, g_frout);
    float* kscp;  cudaGetSymbolAddress((void**)&kscp,  g_ksc_part);
    float* iscp;  cudaGetSymbolAddress((void**)&iscp,  g_isc_part);
    __nv_bfloat16 *tHi, *tLo, *iHi, *iLo, *w2Hi, *w2Lo, *w1Hi, *w1Lo;
    cudaGetSymbolAddress((void**)&tHi,  g_tHi);
    cudaGetSymbolAddress((void**)&tLo,  g_tLo);
    cudaGetSymbolAddress((void**)&iHi,  g_iHi);
    cudaGetSymbolAddress((void**)&iLo,  g_iLo);
    cudaGetSymbolAddress((void**)&w2Hi, g_w2Hi);
    cudaGetSymbolAddress((void**)&w2Lo, g_w2Lo);
    cudaGetSymbolAddress((void**)&w1Hi, g_w1Hi);
    cudaGetSymbolAddress((void**)&w1Lo, g_w1Lo);

    cudaFuncSetAttribute(hmma_tanh_dot, cudaFuncAttributeMaxDynamicSharedMemorySize, HMMA_SMEM);

    prep_kernel<<<HH, 128>>>(ftw, fmw, fmb, fgw);

    // bf16 hi/lo splits
    split4<<<(MROWS_T * HH / 4 + 255) / 256, 256>>>(text, tHi, tLo, MROWS_T * HH / 4);
    split4<<<(NROWS_I * HH / 4 + 255) / 256, 256>>>(img, iHi, iLo, NROWS_I * HH / 4);
    {
        dim3 g(HH / 32, HH / 32, 2);
        tsplit<<<g, dim3(32, 8)>>>(t2w, i1w);
    }

    // i_sc partials (padded rows are zero -> guarded writes)
    {
        dim3 g(MROWS_I / 128, HH / 128);
        hmma_tanh_dot<<<g, 256, HMMA_SMEM>>>(iHi, iLo, w1Hi, w1Lo, a1w + HH, iscp, NROWS_I);
    }
    // k_sc partials
    {
        dim3 g(MROWS_T / 128, HH / 128);
        hmma_tanh_dot<<<g, 256, HMMA_SMEM>>>(tHi, tLo, w2Hi, w2Lo, a2w + HH, kscp, MROWS_T);
    }

    softmax_kernel<<<BB, 256>>>();

    {
        dim3 g(BB, NCB);
        attend_kernel<<<g, 128>>>(text, img);
    }
    {
        dim3 g(NCB, 2);
        small_gemm_tanh<<<g, 256>>>(attI, giw, gib, nI, attT, gtw, gtb, nT);
    }
    gate_mm_kernel<<<BB, 256>>>(ggw, ggb, fgb);
    {
        dim3 g(NCB, 1);
        small_gemm_tanh<<<g, 256>>>(mm, frw, frb, frout, mm, frw, frb, frout);
    }
    out_kernel<<<(BB * SS) / 8, 256>>>(text, out);
}

// round 6
// speedup vs baseline: 3.5796x; 1.2192x over previous
#include <cuda_runtime.h>
#include <cuda_fp16.h>
#include <stdint.h>

#define BB 32
#define SS 512
#define RR 49
#define HH 768
#define NCB 6              // 128-col blocks for attend/small_gemm
#define NPART 24           // 32-col partial groups for the tensor GEMM
#define MROWS_T (BB*SS)    // 16384
#define NROWS_I (BB*RR)    // 1568
#define MROWS_I 1664       // padded to 13*128

// ================= PTX helpers (sm_103-safe: ldmatrix / mma.sync / cp.async) =======
__device__ __forceinline__ uint32_t smem_u32(const void* p) {
    uint32_t a;
    asm("{ .reg .u64 t; cvta.to.shared.u64 t, %1; cvt.u32.u64 %0, t; }" : "=r"(a) : "l"(p));
    return a;
}
#define SMEM_SWIZZLE_128B(x) ((x) ^ (((x) >> 3) & 0x70))

__device__ __forceinline__ void cpa16(uint32_t s, const void* g) {
    asm volatile("cp.async.cg.shared.global [%0], [%1], 16;" :: "r"(s), "l"(g));
}
__device__ __forceinline__ void ldmx4(uint32_t* r, uint32_t addr) {
    asm volatile("ldmatrix.sync.aligned.m8n8.x4.shared.b16 {%0,%1,%2,%3}, [%4];"
                 : "=r"(r[0]), "=r"(r[1]), "=r"(r[2]), "=r"(r[3]) : "r"(addr));
}
__device__ __forceinline__ void mma16816(float* c, const uint32_t* a, uint32_t b0, uint32_t b1) {
    asm volatile(
        "mma.sync.aligned.m16n8k16.row.col.f32.f16.f16.f32 "
        "{%0,%1,%2,%3}, {%4,%5,%6,%7}, {%8,%9}, {%0,%1,%2,%3};"
        : "+f"(c[0]), "+f"(c[1]), "+f"(c[2]), "+f"(c[3])
        : "r"(a[0]), "r"(a[1]), "r"(a[2]), "r"(a[3]), "r"(b0), "r"(b1));
}
__device__ __forceinline__ float fast_tanh(float x) {
    const float e = __expf(2.f * x);
    return 1.f - __fdividef(2.f, e + 1.f);
}

// ================= scratch (device globals) =================
__device__ float g_ksc_part[NPART * MROWS_T];
__device__ float g_isc_part[NPART * NROWS_I];
__device__ __align__(16) float g_vft[HH];
__device__ __align__(16) float g_vfm[HH];
__device__ float g_fmc;
__device__ float g_fmsc[BB];
__device__ __align__(16) float g_frout[BB * HH];
__device__ float g_wimg[BB * RR];
__device__ float g_wtxt[BB * SS];
__device__ __align__(16) float g_attI[BB * HH];
__device__ __align__(16) float g_attT[BB * HH];
__device__ __align__(16) float g_nI[BB * HH];
__device__ __align__(16) float g_nT[BB * HH];
__device__ __align__(16) float g_mm[BB * HH];
// fp16 inputs (single) + weight hi/lo splits (transposed [n][k])
__device__ __align__(16) __half g_tF[MROWS_T * HH];
__device__ __align__(16) __half g_iF[MROWS_I * HH];   // pad rows stay zero
__device__ __align__(16) __half g_w2Hi[HH * HH];
__device__ __align__(16) __half g_w2Lo[HH * HH];
__device__ __align__(16) __half g_w1Hi[HH * HH];
__device__ __align__(16) __half g_w1Lo[HH * HH];

// ================= block reduce helpers =================
__device__ __forceinline__ float bsum(float v, float* sm) {
    int tid = threadIdx.x;
    sm[tid] = v; __syncthreads();
    for (int s = blockDim.x >> 1; s > 0; s >>= 1) {
        if (tid < s) sm[tid] += sm[tid + s];
        __syncthreads();
    }
    float r = sm[0]; __syncthreads();
    return r;
}
__device__ __forceinline__ float bmax(float v, float* sm) {
    int tid = threadIdx.x;
    sm[tid] = v; __syncthreads();
    for (int s = blockDim.x >> 1; s > 0; s >>= 1) {
        if (tid < s) sm[tid] = fmaxf(sm[tid], sm[tid + s]);
        __syncthreads();
    }
    float r = sm[0]; __syncthreads();
    return r;
}

// ================= input conversion: fp32 -> fp16 =================
__global__ __launch_bounds__(256)
void cvt4(const float* __restrict__ x, __half* __restrict__ o, int n4) {
    int i = blockIdx.x * 256 + threadIdx.x;
    if (i >= n4) return;
    float4 v = ((const float4*)x)[i];
    union P { __half h[4]; uint2 u; } H;
    H.h[0] = __float2half(v.x); H.h[1] = __float2half(v.y);
    H.h[2] = __float2half(v.z); H.h[3] = __float2half(v.w);
    ((uint2*)o)[i] = H.u;
}

// transpose + split weights: Ht[n][k] = fp16 hi/lo of W[k][n]; grid (24,24,2), block (32,8)
__global__ void tsplit(const float* __restrict__ W0, const float* __restrict__ W1) {
    __shared__ float t[32][33];
    const float* W = blockIdx.z ? W1 : W0;
    __half* Hi = blockIdx.z ? g_w1Hi : g_w2Hi;
    __half* Lo = blockIdx.z ? g_w1Lo : g_w2Lo;
    const int kb = blockIdx.x * 32, nb = blockIdx.y * 32;
    const int tx = threadIdx.x, ty = threadIdx.y;
#pragma unroll
    for (int i = 0; i < 4; ++i)
        t[ty + 8 * i][tx] = W[(size_t)(kb + ty + 8 * i) * HH + nb + tx];
    __syncthreads();
#pragma unroll
    for (int i = 0; i < 4; ++i) {
        const float v = t[tx][ty + 8 * i];
        const __half h = __float2half(v);
        Hi[(size_t)(nb + ty + 8 * i) * HH + kb + tx] = h;
        Lo[(size_t)(nb + ty + 8 * i) * HH + kb + tx] = __float2half(v - __half2float(h));
    }
}

// ================= prep: rank-1 collapses =================
__global__ void prep_kernel(const float* __restrict__ ftw, const float* __restrict__ fmw,
                            const float* __restrict__ fmb, const float* __restrict__ fgw) {
    __shared__ float red[128];
    const int k = blockIdx.x, tid = threadIdx.x;
    float s1 = 0.f, s2 = 0.f, s3 = 0.f;
    for (int h = tid; h < HH; h += 128) {
        float g1 = fgw[h], g2 = fgw[HH + h];
        s1 += ftw[k * HH + h] * g1;
        s2 += fmw[k * HH + h] * g2;
        if (k == 0) s3 += fmb[h] * g2;
    }
    float t1 = bsum(s1, red);
    float t2 = bsum(s2, red);
    if (tid == 0) { g_vft[k] = t1; g_vfm[k] = t2; }
    if (k == 0) {
        float t3 = bsum(s3, red);
        if (tid == 0) g_fmc = t3;
    }
}

// ================= fused 2-pass fp16 HMMA GEMM + tanh + dot epilogue =================
// C[128x128] per CTA; per K-chunk of 64: load {A, Whi, Wlo}, MMA into one acc.
// smem: 2 stages x {A 16K, Bhi 16K, Blo 16K} = 96 KB.
#define HMMA_SMEM (96 * 1024)

__device__ __forceinline__ void issue_chunk(
    const __half* __restrict__ Ap, const __half* __restrict__ BHi,
    const __half* __restrict__ BLo,
    int kt, uint32_t stageBase, int tid, int rowBase, int colBase) {
#pragma unroll
    for (int i = 0; i < 4; i++) {
        int u = tid + i * 256;                 // 1024 x 16B units
        cpa16(stageBase + SMEM_SWIZZLE_128B((uint32_t)u * 16u),
              Ap + (size_t)(rowBase + (u >> 3)) * HH + kt + (u & 7) * 8);
    }
#pragma unroll
    for (int i = 0; i < 4; i++) {
        int u = tid + i * 256;
        cpa16(stageBase + 16384u + SMEM_SWIZZLE_128B((uint32_t)u * 16u),
              BHi + (size_t)(colBase + (u >> 3)) * HH + kt + (u & 7) * 8);
    }
#pragma unroll
    for (int i = 0; i < 4; i++) {
        int u = tid + i * 256;
        cpa16(stageBase + 32768u + SMEM_SWIZZLE_128B((uint32_t)u * 16u),
              BLo + (size_t)(colBase + (u >> 3)) * HH + kt + (u & 7) * 8);
    }
    asm volatile("cp.async.commit_group;");
}

__global__ __launch_bounds__(256, 2)
void hmma_tanh_dot(const __half* __restrict__ A, const __half* __restrict__ WHi,
                   const __half* __restrict__ WLo,
                   const float* __restrict__ av, float* __restrict__ outPart, int nrows) {
    extern __shared__ __align__(1024) char smem[];
    const uint32_t sb = smem_u32(smem);
    const int tid = threadIdx.x;
    const int wid = tid >> 5, lane = tid & 31;
    const int warpm = wid & 1, warpn = wid >> 1;   // 2 x 4 warp grid, warp tile 64x32
    const int rowBase = blockIdx.x * 128;
    const int colBase = blockIdx.y * 128;

    float acc[4][4][4];
#pragma unroll
    for (int i = 0; i < 4; i++)
#pragma unroll
        for (int j = 0; j < 4; j++)
#pragma unroll
            for (int q = 0; q < 4; q++) acc[i][j][q] = 0.f;

    issue_chunk(A, WHi, WLo, 0, sb, tid, rowBase, colBase);

    for (int it = 0; it < 12; ++it) {
        if (it < 11) {
            issue_chunk(A, WHi, WLo, (it + 1) * 64, sb + ((it + 1) & 1) * 49152u,
                        tid, rowBase, colBase);
            asm volatile("cp.async.wait_group 1;");
        } else {
            asm volatile("cp.async.wait_group 0;");
        }
        __syncthreads();

        const uint32_t abase = sb + (it & 1) * 49152u;
        const uint32_t hbase = abase + 16384u;
        const uint32_t lbase = abase + 32768u;
#pragma unroll
        for (int ks = 0; ks < 4; ++ks) {
            uint32_t bh[2][4], bl[2][4];
#pragma unroll
            for (int g = 0; g < 2; ++g) {
                const int n = warpn * 32 + g * 16 + (lane & 7) + ((lane >> 4) << 3);
                const int kb = ks * 32 + ((lane >> 3) & 1) * 16;
                const uint32_t sw = SMEM_SWIZZLE_128B((uint32_t)(n * 128 + kb));
                ldmx4(bh[g], hbase + sw);
                ldmx4(bl[g], lbase + sw);
            }
#pragma unroll
            for (int mt = 0; mt < 4; ++mt) {
                uint32_t a[4];
                const int r = warpm * 64 + mt * 16 + (lane & 15);
                const int kb = ks * 32 + ((lane >> 4) << 4);
                ldmx4(a, abase + SMEM_SWIZZLE_128B((uint32_t)(r * 128 + kb)));
#pragma unroll
                for (int nt = 0; nt < 4; ++nt)
                    mma16816(acc[mt][nt], a, bh[nt >> 1][(nt & 1) * 2],
                             bh[nt >> 1][(nt & 1) * 2 + 1]);
#pragma unroll
                for (int nt = 0; nt < 4; ++nt)
                    mma16816(acc[mt][nt], a, bl[nt >> 1][(nt & 1) * 2],
                             bl[nt >> 1][(nt & 1) * 2 + 1]);
            }
        }
        __syncthreads();
    }

    // ---- epilogue: tanh * av, reduce over this warp's 32 cols, write row partials ----
    const float* avp = av + colBase + warpn * 32;
    float avv[4][2];
#pragma unroll
    for (int nt = 0; nt < 4; ++nt) {
        avv[nt][0] = avp[nt * 8 + (lane & 3) * 2];
        avv[nt][1] = avp[nt * 8 + (lane & 3) * 2 + 1];
    }
    const int gcol = blockIdx.y * 4 + warpn;
#pragma unroll
    for (int mt = 0; mt < 4; ++mt) {
        float s0 = 0.f, s1 = 0.f;
#pragma unroll
        for (int nt = 0; nt < 4; ++nt) {
            s0 += fast_tanh(acc[mt][nt][0]) * avv[nt][0] + fast_tanh(acc[mt][nt][1]) * avv[nt][1];
            s1 += fast_tanh(acc[mt][nt][2]) * avv[nt][0] + fast_tanh(acc[mt][nt][3]) * avv[nt][1];
        }
        s0 += __shfl_xor_sync(0xffffffffu, s0, 1);
        s0 += __shfl_xor_sync(0xffffffffu, s0, 2);
        s1 += __shfl_xor_sync(0xffffffffu, s1, 1);
        s1 += __shfl_xor_sync(0xffffffffu, s1, 2);
        if ((lane & 3) == 0) {
            const int r0 = rowBase + warpm * 64 + mt * 16 + (lane >> 2);
            if (r0 < nrows) outPart[gcol * nrows + r0] = s0;
            if (r0 + 8 < nrows) outPart[gcol * nrows + r0 + 8] = s1;
        }
    }
}

// ================= softmaxes =================
__global__ void softmax_kernel() {
    __shared__ float red[256];
    __shared__ float w[SS];
    const int b = blockIdx.x, tid = threadIdx.x;

    float s0 = -1e30f;
    if (tid < RR) {
        float s = 0.f;
#pragma unroll
        for (int c = 0; c < NPART; c++) s += g_isc_part[c * NROWS_I + b * RR + tid];
        w[tid] = s; s0 = s;
    }
    float mx = bmax(s0, red);
    float ex = 0.f;
    if (tid < RR) ex = expf(w[tid] - mx);
    float tot = bsum(ex, red);
    if (tid < RR) g_wimg[b * RR + tid] = ex / tot;

    float mx2 = -1e30f;
    for (int j = tid; j < SS; j += 256) {
        float s = 0.f;
#pragma unroll
        for (int c = 0; c < NPART; c++) s += g_ksc_part[c * MROWS_T + b * SS + j];
        w[j] = s; mx2 = fmaxf(mx2, s);
    }
    mx2 = bmax(mx2, red);
    float es = 0.f;
    for (int j = tid; j < SS; j += 256) { float e = expf(w[j] - mx2); w[j] = e; es += e; }
    tot = bsum(es, red);
    float inv = 1.f / tot;
    for (int j = tid; j < SS; j += 256) g_wtxt[b * SS + j] = w[j] * inv;
}

// ================= attended vectors =================
__global__ __launch_bounds__(128)
void attend_kernel(const float* __restrict__ text, const float* __restrict__ img) {
    __shared__ float wt[SS];
    __shared__ float wi[RR];
    const int b = blockIdx.x, tid = threadIdx.x;
    const int h = blockIdx.y * 128 + tid;

    for (int j = tid; j < SS; j += 128) wt[j] = g_wtxt[b * SS + j];
    if (tid < RR) wi[tid] = g_wimg[b * RR + tid];
    __syncthreads();

    {
        const float* tp = text + b * SS * HH + h;
        float a0 = 0.f, a1 = 0.f, a2 = 0.f, a3 = 0.f;
#pragma unroll 4
        for (int j = 0; j < SS; j += 4) {
            a0 += wt[j + 0] * tp[(j + 0) * HH];
            a1 += wt[j + 1] * tp[(j + 1) * HH];
            a2 += wt[j + 2] * tp[(j + 2) * HH];
            a3 += wt[j + 3] * tp[(j + 3) * HH];
        }
        g_attT[b * HH + h] = (a0 + a1) + (a2 + a3);
    }
    {
        const float* ip = img + b * RR * HH + h;
        float a = 0.f;
#pragma unroll
        for (int r = 0; r < RR; r++) a += wi[r] * ip[r * HH];
        g_attI[b * HH + h] = a;
    }
}

// ================= small GEMM: C[32,768] = tanh(A @ W + bias) =================
__global__ __launch_bounds__(256)
void small_gemm_tanh(const float* __restrict__ A0, const float* __restrict__ W0,
                     const float* __restrict__ b0, float* __restrict__ C0,
                     const float* __restrict__ A1, const float* __restrict__ W1,
                     const float* __restrict__ b1, float* __restrict__ C1) {
    const float* A = blockIdx.y ? A1 : A0;
    const float* W = blockIdx.y ? W1 : W0;
    const float* bias = blockIdx.y ? b1 : b0;
    float* C = blockIdx.y ? C1 : C0;

    __shared__ __align__(16) float As[32][36];
    __shared__ __align__(16) float Ws[32][128];
    const int tid = threadIdx.x;
    const int colBase = blockIdx.x * 128;
    const int tx = tid & 31;
    const int ty = tid >> 5;

    float acc[4][4];
#pragma unroll
    for (int i = 0; i < 4; i++)
#pragma unroll
        for (int j = 0; j < 4; j++) acc[i][j] = 0.f;

    for (int kt = 0; kt < HH; kt += 32) {
        {
            int r = tid >> 3;
            int kg = (tid & 7) << 2;
            float4 v = *(const float4*)(A + r * HH + kt + kg);
            As[kg + 0][r] = v.x; As[kg + 1][r] = v.y;
            As[kg + 2][r] = v.z; As[kg + 3][r] = v.w;
        }
#pragma unroll
        for (int i = 0; i < 4; i++) {
            int idx = tid + i * 256;
            int kk = idx >> 5;
            int ng = (idx & 31) << 2;
            *(float4*)&Ws[kk][ng] = *(const float4*)(W + (kt + kk) * HH + colBase + ng);
        }
        __syncthreads();
#pragma unroll
        for (int k = 0; k < 32; k++) {
            float4 av4 = *(const float4*)&As[k][ty * 4];
            float4 w = *(const float4*)&Ws[k][tx * 4];
            float a[4] = {av4.x, av4.y, av4.z, av4.w};
#pragma unroll
            for (int i = 0; i < 4; i++) {
                acc[i][0] = fmaf(a[i], w.x, acc[i][0]);
                acc[i][1] = fmaf(a[i], w.y, acc[i][1]);
                acc[i][2] = fmaf(a[i], w.z, acc[i][2]);
                acc[i][3] = fmaf(a[i], w.w, acc[i][3]);
            }
        }
        __syncthreads();
    }

    int col = colBase + tx * 4;
    float4 bv = *(const float4*)(bias + col);
#pragma unroll
    for (int i = 0; i < 4; i++) {
        int row = ty * 4 + i;
        float4 o;
        o.x = tanhf(acc[i][0] + bv.x);
        o.y = tanhf(acc[i][1] + bv.y);
        o.z = tanhf(acc[i][2] + bv.z);
        o.w = tanhf(acc[i][3] + bv.w);
        *(float4*)(C + row * HH + col) = o;
    }
}

// ================= gate + multimodal + fm score =================
__global__ void gate_mm_kernel(const float* __restrict__ ggw, const float* __restrict__ ggb,
                               const float* __restrict__ fgb) {
    __shared__ float red[256];
    const int b = blockIdx.x, tid = threadIdx.x;

    float gp = 0.f;
    for (int h = tid; h < HH; h += 256)
        gp += g_nI[b * HH + h] * ggw[h] + g_nT[b * HH + h] * ggw[HH + h];
    float gs = bsum(gp, red);
    float gate = 1.f / (1.f + expf(-(gs + ggb[0])));

    float fmp = 0.f;
    for (int h = tid; h < HH; h += 256) {
        float v = gate * g_nI[b * HH + h] + (1.f - gate) * g_nT[b * HH + h];
        g_mm[b * HH + h] = v;
        fmp += v * g_vfm[h];
    }
    float fsum = bsum(fmp, red);
    if (tid == 0) g_fmsc[b] = fsum + g_fmc + fgb[0];
}

// ================= output: warp per row =================
__global__ __launch_bounds__(256)
void out_kernel(const float* __restrict__ text, float* __restrict__ out) {
    const int warp = threadIdx.x >> 5;
    const int lane = threadIdx.x & 31;
    const int row = blockIdx.x * 8 + warp;
    const int b = row >> 9;

    const float4* tv = (const float4*)(text + row * HH);
    const float4* vv = (const float4*)g_vft;
    float p = 0.f;
#pragma unroll
    for (int i = 0; i < 6; i++) {
        float4 t = tv[lane + i * 32];
        float4 v = vv[lane + i * 32];
        p += t.x * v.x + t.y * v.y + t.z * v.z + t.w * v.w;
    }
#pragma unroll
    for (int off = 16; off > 0; off >>= 1) p += __shfl_xor_sync(0xffffffffu, p, off);
    float fg = 1.f / (1.f + expf(-(p + g_fmsc[b])));

    const float4* fr = (const float4*)(g_frout + b * HH);
    float4* op = (float4*)(out + row * HH);
#pragma unroll
    for (int i = 0; i < 6; i++) {
        float4 f = fr[lane + i * 32];
        float4 o;
        o.x = fg * f.x; o.y = fg * f.y; o.z = fg * f.z; o.w = fg * f.w;
        op[lane + i * 32] = o;
    }
}

// ================= launch =================
extern "C" void kernel_launch(void* const* d_in, const int* in_sizes, int n_in,
                              void* d_out, int out_size) {
    const float* text = (const float*)d_in[0];
    const float* img  = (const float*)d_in[1];
    const float* i1w  = (const float*)d_in[4];
    const float* a1w  = (const float*)d_in[5];
    const float* t2w  = (const float*)d_in[7];
    const float* a2w  = (const float*)d_in[10];
    const float* gtw  = (const float*)d_in[12];
    const float* gtb  = (const float*)d_in[13];
    const float* giw  = (const float*)d_in[14];
    const float* gib  = (const float*)d_in[15];
    const float* ggw  = (const float*)d_in[16];
    const float* ggb  = (const float*)d_in[17];
    const float* ftw  = (const float*)d_in[18];
    const float* fmw  = (const float*)d_in[19];
    const float* fmb  = (const float*)d_in[20];
    const float* fgw  = (const float*)d_in[21];
    const float* fgb  = (const float*)d_in[22];
    const float* frw  = (const float*)d_in[23];
    const float* frb  = (const float*)d_in[24];
    float* out = (float*)d_out;

    float* attI;  cudaGetSymbolAddress((void**)&attI,  g_attI);
    float* attT;  cudaGetSymbolAddress((void**)&attT,  g_attT);
    float* nI;    cudaGetSymbolAddress((void**)&nI,    g_nI);
    float* nT;    cudaGetSymbolAddress((void**)&nT,    g_nT);
    float* mm;    cudaGetSymbolAddress((void**)&mm,    g_mm);
    float* frout; cudaGetSymbolAddress((void**)&frout, g_frout);
    float* kscp;  cudaGetSymbolAddress((void**)&kscp,  g_ksc_part);
    float* iscp;  cudaGetSymbolAddress((void**)&iscp,  g_isc_part);
    __half *tF, *iF, *w2Hi, *w2Lo, *w1Hi, *w1Lo;
    cudaGetSymbolAddress((void**)&tF,   g_tF);
    cudaGetSymbolAddress((void**)&iF,   g_iF);
    cudaGetSymbolAddress((void**)&w2Hi, g_w2Hi);
    cudaGetSymbolAddress((void**)&w2Lo, g_w2Lo);
    cudaGetSymbolAddress((void**)&w1Hi, g_w1Hi);
    cudaGetSymbolAddress((void**)&w1Lo, g_w1Lo);

    cudaFuncSetAttribute(hmma_tanh_dot, cudaFuncAttributeMaxDynamicSharedMemorySize, HMMA_SMEM);

    prep_kernel<<<HH, 128>>>(ftw, fmw, fmb, fgw);

    // fp16 conversions / weight splits
    cvt4<<<(MROWS_T * HH / 4 + 255) / 256, 256>>>(text, tF, MROWS_T * HH / 4);
    cvt4<<<(NROWS_I * HH / 4 + 255) / 256, 256>>>(img, iF, NROWS_I * HH / 4);
    {
        dim3 g(HH / 32, HH / 32, 2);
        tsplit<<<g, dim3(32, 8)>>>(t2w, i1w);
    }

    // i_sc partials (padded rows are zero -> guarded writes)
    {
        dim3 g(MROWS_I / 128, HH / 128);
        hmma_tanh_dot<<<g, 256, HMMA_SMEM>>>(iF, w1Hi, w1Lo, a1w + HH, iscp, NROWS_I);
    }
    // k_sc partials
    {
        dim3 g(MROWS_T / 128, HH / 128);
        hmma_tanh_dot<<<g, 256, HMMA_SMEM>>>(tF, w2Hi, w2Lo, a2w + HH, kscp, MROWS_T);
    }

    softmax_kernel<<<BB, 256>>>();

    {
        dim3 g(BB, NCB);
        attend_kernel<<<g, 128>>>(text, img);
    }
    {
        dim3 g(NCB, 2);
        small_gemm_tanh<<<g, 256>>>(attI, giw, gib, nI, attT, gtw, gtb, nT);
    }
    gate_mm_kernel<<<BB, 256>>>(ggw, ggb, fgb);
    {
        dim3 g(NCB, 1);
        small_gemm_tanh<<<g, 256>>>(mm, frw, frb, frout, mm, frw, frb, frout);
    }
    out_kernel<<<(BB * SS) / 8, 256>>>(text, out);
}

// round 7
// speedup vs baseline: 4.3271x; 1.2088x over previous
#include <cuda_runtime.h>
#include <cuda_fp16.h>
#include <stdint.h>

#define BB 32
#define SS 512
#define RR 49
#define HH 768
#define NCB 6              // 128-col blocks for attend/small_gemm
#define NPART 24           // 32-col partial groups for the tensor GEMM
#define MROWS_T (BB*SS)    // 16384
#define NROWS_I (BB*RR)    // 1568
#define MROWS_I 1664       // padded to 13*128

// ================= PTX helpers (sm_103-safe: ldmatrix / mma.sync / cp.async) =======
__device__ __forceinline__ uint32_t smem_u32(const void* p) {
    uint32_t a;
    asm("{ .reg .u64 t; cvta.to.shared.u64 t, %1; cvt.u32.u64 %0, t; }" : "=r"(a) : "l"(p));
    return a;
}
#define SMEM_SWIZZLE_128B(x) ((x) ^ (((x) >> 3) & 0x70))

__device__ __forceinline__ void cpa16(uint32_t s, const void* g) {
    asm volatile("cp.async.cg.shared.global [%0], [%1], 16;" :: "r"(s), "l"(g));
}
__device__ __forceinline__ void ldmx4(uint32_t* r, uint32_t addr) {
    asm volatile("ldmatrix.sync.aligned.m8n8.x4.shared.b16 {%0,%1,%2,%3}, [%4];"
                 : "=r"(r[0]), "=r"(r[1]), "=r"(r[2]), "=r"(r[3]) : "r"(addr));
}
__device__ __forceinline__ void mma16816(float* c, const uint32_t* a, uint32_t b0, uint32_t b1) {
    asm volatile(
        "mma.sync.aligned.m16n8k16.row.col.f32.f16.f16.f32 "
        "{%0,%1,%2,%3}, {%4,%5,%6,%7}, {%8,%9}, {%0,%1,%2,%3};"
        : "+f"(c[0]), "+f"(c[1]), "+f"(c[2]), "+f"(c[3])
        : "r"(a[0]), "r"(a[1]), "r"(a[2]), "r"(a[3]), "r"(b0), "r"(b1));
}
__device__ __forceinline__ float fast_tanh(float x) {
    const float e = __expf(2.f * x);
    return 1.f - __fdividef(2.f, e + 1.f);
}

// ================= scratch (device globals) =================
__device__ float g_ksc_part[NPART * MROWS_T];
__device__ float g_isc_part[NPART * NROWS_I];
__device__ __align__(16) float g_vft[HH];
__device__ __align__(16) float g_vfm[HH];
__device__ float g_fmc;
__device__ float g_fmsc[BB];
__device__ __align__(16) float g_frout[BB * HH];
__device__ float g_wimg[BB * RR];
__device__ float g_wtxt[BB * SS];
__device__ __align__(16) float g_attI[BB * HH];
__device__ __align__(16) float g_attT[BB * HH];
__device__ __align__(16) float g_nI[BB * HH];
__device__ __align__(16) float g_nT[BB * HH];
__device__ __align__(16) float g_mm[BB * HH];
// fp16 inputs + weights (transposed [n][k])
__device__ __align__(16) __half g_tF[MROWS_T * HH];
__device__ __align__(16) __half g_iF[MROWS_I * HH];   // pad rows stay zero
__device__ __align__(16) __half g_w2[HH * HH];
__device__ __align__(16) __half g_w1[HH * HH];

// ================= block reduce helpers =================
__device__ __forceinline__ float bsum(float v, float* sm) {
    int tid = threadIdx.x;
    sm[tid] = v; __syncthreads();
    for (int s = blockDim.x >> 1; s > 0; s >>= 1) {
        if (tid < s) sm[tid] += sm[tid + s];
        __syncthreads();
    }
    float r = sm[0]; __syncthreads();
    return r;
}
__device__ __forceinline__ float bmax(float v, float* sm) {
    int tid = threadIdx.x;
    sm[tid] = v; __syncthreads();
    for (int s = blockDim.x >> 1; s > 0; s >>= 1) {
        if (tid < s) sm[tid] = fmaxf(sm[tid], sm[tid + s]);
        __syncthreads();
    }
    float r = sm[0]; __syncthreads();
    return r;
}

// ================= input conversion: fp32 -> fp16 =================
__global__ __launch_bounds__(256)
void cvt4(const float* __restrict__ x, __half* __restrict__ o, int n4) {
    int i = blockIdx.x * 256 + threadIdx.x;
    if (i >= n4) return;
    float4 v = ((const float4*)x)[i];
    union P { __half h[4]; uint2 u; } H;
    H.h[0] = __float2half(v.x); H.h[1] = __float2half(v.y);
    H.h[2] = __float2half(v.z); H.h[3] = __float2half(v.w);
    ((uint2*)o)[i] = H.u;
}

// transpose + convert weights: Ht[n][k] = fp16(W[k][n]); grid (24,24,2), block (32,8)
__global__ void tcvt(const float* __restrict__ W0, const float* __restrict__ W1) {
    __shared__ float t[32][33];
    const float* W = blockIdx.z ? W1 : W0;
    __half* Hi = blockIdx.z ? g_w1 : g_w2;
    const int kb = blockIdx.x * 32, nb = blockIdx.y * 32;
    const int tx = threadIdx.x, ty = threadIdx.y;
#pragma unroll
    for (int i = 0; i < 4; ++i)
        t[ty + 8 * i][tx] = W[(size_t)(kb + ty + 8 * i) * HH + nb + tx];
    __syncthreads();
#pragma unroll
    for (int i = 0; i < 4; ++i)
        Hi[(size_t)(nb + ty + 8 * i) * HH + kb + tx] = __float2half(t[tx][ty + 8 * i]);
}

// ================= prep: rank-1 collapses =================
__global__ void prep_kernel(const float* __restrict__ ftw, const float* __restrict__ fmw,
                            const float* __restrict__ fmb, const float* __restrict__ fgw) {
    __shared__ float red[128];
    const int k = blockIdx.x, tid = threadIdx.x;
    float s1 = 0.f, s2 = 0.f, s3 = 0.f;
    for (int h = tid; h < HH; h += 128) {
        float g1 = fgw[h], g2 = fgw[HH + h];
        s1 += ftw[k * HH + h] * g1;
        s2 += fmw[k * HH + h] * g2;
        if (k == 0) s3 += fmb[h] * g2;
    }
    float t1 = bsum(s1, red);
    float t2 = bsum(s2, red);
    if (tid == 0) { g_vft[k] = t1; g_vfm[k] = t2; }
    if (k == 0) {
        float t3 = bsum(s3, red);
        if (tid == 0) g_fmc = t3;
    }
}

// ================= single-pass fp16 HMMA GEMM + tanh + dot epilogue =================
// C[128x128] per CTA; K=768 in 12 chunks of 64; 3-stage cp.async pipeline.
// smem: 3 stages x {A 16K, B 16K} = 96 KB.
#define HMMA_SMEM (96 * 1024)

__device__ __forceinline__ void issue_chunk(
    const __half* __restrict__ Ap, const __half* __restrict__ Bp,
    int kt, uint32_t stageBase, int tid, int rowBase, int colBase) {
#pragma unroll
    for (int i = 0; i < 4; i++) {
        int u = tid + i * 256;                 // 1024 x 16B units
        cpa16(stageBase + SMEM_SWIZZLE_128B((uint32_t)u * 16u),
              Ap + (size_t)(rowBase + (u >> 3)) * HH + kt + (u & 7) * 8);
    }
#pragma unroll
    for (int i = 0; i < 4; i++) {
        int u = tid + i * 256;
        cpa16(stageBase + 16384u + SMEM_SWIZZLE_128B((uint32_t)u * 16u),
              Bp + (size_t)(colBase + (u >> 3)) * HH + kt + (u & 7) * 8);
    }
    asm volatile("cp.async.commit_group;");
}

__global__ __launch_bounds__(256, 2)
void hmma_tanh_dot(const __half* __restrict__ A, const __half* __restrict__ W,
                   const float* __restrict__ av, float* __restrict__ outPart, int nrows) {
    extern __shared__ __align__(1024) char smem[];
    const uint32_t sb = smem_u32(smem);
    const int tid = threadIdx.x;
    const int wid = tid >> 5, lane = tid & 31;
    const int warpm = wid & 1, warpn = wid >> 1;   // 2 x 4 warp grid, warp tile 64x32
    const int rowBase = blockIdx.x * 128;
    const int colBase = blockIdx.y * 128;

    float acc[4][4][4];
#pragma unroll
    for (int i = 0; i < 4; i++)
#pragma unroll
        for (int j = 0; j < 4; j++)
#pragma unroll
            for (int q = 0; q < 4; q++) acc[i][j][q] = 0.f;

    issue_chunk(A, W, 0, sb, tid, rowBase, colBase);
    issue_chunk(A, W, 64, sb + 32768u, tid, rowBase, colBase);

    for (int it = 0; it < 12; ++it) {
        if (it < 10) {
            const int nx = it + 2;
            issue_chunk(A, W, nx * 64, sb + (uint32_t)(nx % 3) * 32768u,
                        tid, rowBase, colBase);
            asm volatile("cp.async.wait_group 2;");
        } else if (it == 10) {
            asm volatile("cp.async.wait_group 1;");
        } else {
            asm volatile("cp.async.wait_group 0;");
        }
        __syncthreads();

        const uint32_t abase = sb + (uint32_t)(it % 3) * 32768u;
        const uint32_t bbase = abase + 16384u;
#pragma unroll
        for (int ks = 0; ks < 4; ++ks) {
            uint32_t bf[2][4];
#pragma unroll
            for (int g = 0; g < 2; ++g) {
                const int n = warpn * 32 + g * 16 + (lane & 7) + ((lane >> 4) << 3);
                const int kb = ks * 32 + ((lane >> 3) & 1) * 16;
                ldmx4(bf[g], bbase + SMEM_SWIZZLE_128B((uint32_t)(n * 128 + kb)));
            }
#pragma unroll
            for (int mt = 0; mt < 4; ++mt) {
                uint32_t a[4];
                const int r = warpm * 64 + mt * 16 + (lane & 15);
                const int kb = ks * 32 + ((lane >> 4) << 4);
                ldmx4(a, abase + SMEM_SWIZZLE_128B((uint32_t)(r * 128 + kb)));
#pragma unroll
                for (int nt = 0; nt < 4; ++nt)
                    mma16816(acc[mt][nt], a, bf[nt >> 1][(nt & 1) * 2],
                             bf[nt >> 1][(nt & 1) * 2 + 1]);
            }
        }
        __syncthreads();
    }

    // ---- epilogue: tanh * av, reduce over this warp's 32 cols, write row partials ----
    const float* avp = av + colBase + warpn * 32;
    float avv[4][2];
#pragma unroll
    for (int nt = 0; nt < 4; ++nt) {
        avv[nt][0] = avp[nt * 8 + (lane & 3) * 2];
        avv[nt][1] = avp[nt * 8 + (lane & 3) * 2 + 1];
    }
    const int gcol = blockIdx.y * 4 + warpn;
#pragma unroll
    for (int mt = 0; mt < 4; ++mt) {
        float s0 = 0.f, s1 = 0.f;
#pragma unroll
        for (int nt = 0; nt < 4; ++nt) {
            s0 += fast_tanh(acc[mt][nt][0]) * avv[nt][0] + fast_tanh(acc[mt][nt][1]) * avv[nt][1];
            s1 += fast_tanh(acc[mt][nt][2]) * avv[nt][0] + fast_tanh(acc[mt][nt][3]) * avv[nt][1];
        }
        s0 += __shfl_xor_sync(0xffffffffu, s0, 1);
        s0 += __shfl_xor_sync(0xffffffffu, s0, 2);
        s1 += __shfl_xor_sync(0xffffffffu, s1, 1);
        s1 += __shfl_xor_sync(0xffffffffu, s1, 2);
        if ((lane & 3) == 0) {
            const int r0 = rowBase + warpm * 64 + mt * 16 + (lane >> 2);
            if (r0 < nrows) outPart[gcol * nrows + r0] = s0;
            if (r0 + 8 < nrows) outPart[gcol * nrows + r0 + 8] = s1;
        }
    }
}

// ================= softmaxes =================
__global__ void softmax_kernel() {
    __shared__ float red[256];
    __shared__ float w[SS];
    const int b = blockIdx.x, tid = threadIdx.x;

    float s0 = -1e30f;
    if (tid < RR) {
        float s = 0.f;
#pragma unroll
        for (int c = 0; c < NPART; c++) s += g_isc_part[c * NROWS_I + b * RR + tid];
        w[tid] = s; s0 = s;
    }
    float mx = bmax(s0, red);
    float ex = 0.f;
    if (tid < RR) ex = expf(w[tid] - mx);
    float tot = bsum(ex, red);
    if (tid < RR) g_wimg[b * RR + tid] = ex / tot;

    float mx2 = -1e30f;
    for (int j = tid; j < SS; j += 256) {
        float s = 0.f;
#pragma unroll
        for (int c = 0; c < NPART; c++) s += g_ksc_part[c * MROWS_T + b * SS + j];
        w[j] = s; mx2 = fmaxf(mx2, s);
    }
    mx2 = bmax(mx2, red);
    float es = 0.f;
    for (int j = tid; j < SS; j += 256) { float e = expf(w[j] - mx2); w[j] = e; es += e; }
    tot = bsum(es, red);
    float inv = 1.f / tot;
    for (int j = tid; j < SS; j += 256) g_wtxt[b * SS + j] = w[j] * inv;
}

// ================= attended vectors =================
__global__ __launch_bounds__(128)
void attend_kernel(const float* __restrict__ text, const float* __restrict__ img) {
    __shared__ float wt[SS];
    __shared__ float wi[RR];
    const int b = blockIdx.x, tid = threadIdx.x;
    const int h = blockIdx.y * 128 + tid;

    for (int j = tid; j < SS; j += 128) wt[j] = g_wtxt[b * SS + j];
    if (tid < RR) wi[tid] = g_wimg[b * RR + tid];
    __syncthreads();

    {
        const float* tp = text + b * SS * HH + h;
        float a0 = 0.f, a1 = 0.f, a2 = 0.f, a3 = 0.f;
#pragma unroll 4
        for (int j = 0; j < SS; j += 4) {
            a0 += wt[j + 0] * tp[(j + 0) * HH];
            a1 += wt[j + 1] * tp[(j + 1) * HH];
            a2 += wt[j + 2] * tp[(j + 2) * HH];
            a3 += wt[j + 3] * tp[(j + 3) * HH];
        }
        g_attT[b * HH + h] = (a0 + a1) + (a2 + a3);
    }
    {
        const float* ip = img + b * RR * HH + h;
        float a = 0.f;
#pragma unroll
        for (int r = 0; r < RR; r++) a += wi[r] * ip[r * HH];
        g_attI[b * HH + h] = a;
    }
}

// ================= small GEMM: C[32,768] = tanh(A @ W + bias) =================
__global__ __launch_bounds__(256)
void small_gemm_tanh(const float* __restrict__ A0, const float* __restrict__ W0,
                     const float* __restrict__ b0, float* __restrict__ C0,
                     const float* __restrict__ A1, const float* __restrict__ W1,
                     const float* __restrict__ b1, float* __restrict__ C1) {
    const float* A = blockIdx.y ? A1 : A0;
    const float* W = blockIdx.y ? W1 : W0;
    const float* bias = blockIdx.y ? b1 : b0;
    float* C = blockIdx.y ? C1 : C0;

    __shared__ __align__(16) float As[32][36];
    __shared__ __align__(16) float Ws[32][128];
    const int tid = threadIdx.x;
    const int colBase = blockIdx.x * 128;
    const int tx = tid & 31;
    const int ty = tid >> 5;

    float acc[4][4];
#pragma unroll
    for (int i = 0; i < 4; i++)
#pragma unroll
        for (int j = 0; j < 4; j++) acc[i][j] = 0.f;

    for (int kt = 0; kt < HH; kt += 32) {
        {
            int r = tid >> 3;
            int kg = (tid & 7) << 2;
            float4 v = *(const float4*)(A + r * HH + kt + kg);
            As[kg + 0][r] = v.x; As[kg + 1][r] = v.y;
            As[kg + 2][r] = v.z; As[kg + 3][r] = v.w;
        }
#pragma unroll
        for (int i = 0; i < 4; i++) {
            int idx = tid + i * 256;
            int kk = idx >> 5;
            int ng = (idx & 31) << 2;
            *(float4*)&Ws[kk][ng] = *(const float4*)(W + (kt + kk) * HH + colBase + ng);
        }
        __syncthreads();
#pragma unroll
        for (int k = 0; k < 32; k++) {
            float4 av4 = *(const float4*)&As[k][ty * 4];
            float4 w = *(const float4*)&Ws[k][tx * 4];
            float a[4] = {av4.x, av4.y, av4.z, av4.w};
#pragma unroll
            for (int i = 0; i < 4; i++) {
                acc[i][0] = fmaf(a[i], w.x, acc[i][0]);
                acc[i][1] = fmaf(a[i], w.y, acc[i][1]);
                acc[i][2] = fmaf(a[i], w.z, acc[i][2]);
                acc[i][3] = fmaf(a[i], w.w, acc[i][3]);
            }
        }
        __syncthreads();
    }

    int col = colBase + tx * 4;
    float4 bv = *(const float4*)(bias + col);
#pragma unroll
    for (int i = 0; i < 4; i++) {
        int row = ty * 4 + i;
        float4 o;
        o.x = tanhf(acc[i][0] + bv.x);
        o.y = tanhf(acc[i][1] + bv.y);
        o.z = tanhf(acc[i][2] + bv.z);
        o.w = tanhf(acc[i][3] + bv.w);
        *(float4*)(C + row * HH + col) = o;
    }
}

// ================= gate + multimodal + fm score =================
__global__ void gate_mm_kernel(const float* __restrict__ ggw, const float* __restrict__ ggb,
                               const float* __restrict__ fgb) {
    __shared__ float red[256];
    const int b = blockIdx.x, tid = threadIdx.x;

    float gp = 0.f;
    for (int h = tid; h < HH; h += 256)
        gp += g_nI[b * HH + h] * ggw[h] + g_nT[b * HH + h] * ggw[HH + h];
    float gs = bsum(gp, red);
    float gate = 1.f / (1.f + expf(-(gs + ggb[0])));

    float fmp = 0.f;
    for (int h = tid; h < HH; h += 256) {
        float v = gate * g_nI[b * HH + h] + (1.f - gate) * g_nT[b * HH + h];
        g_mm[b * HH + h] = v;
        fmp += v * g_vfm[h];
    }
    float fsum = bsum(fmp, red);
    if (tid == 0) g_fmsc[b] = fsum + g_fmc + fgb[0];
}

// ================= output: warp per row =================
__global__ __launch_bounds__(256)
void out_kernel(const float* __restrict__ text, float* __restrict__ out) {
    const int warp = threadIdx.x >> 5;
    const int lane = threadIdx.x & 31;
    const int row = blockIdx.x * 8 + warp;
    const int b = row >> 9;

    const float4* tv = (const float4*)(text + row * HH);
    const float4* vv = (const float4*)g_vft;
    float p = 0.f;
#pragma unroll
    for (int i = 0; i < 6; i++) {
        float4 t = tv[lane + i * 32];
        float4 v = vv[lane + i * 32];
        p += t.x * v.x + t.y * v.y + t.z * v.z + t.w * v.w;
    }
#pragma unroll
    for (int off = 16; off > 0; off >>= 1) p += __shfl_xor_sync(0xffffffffu, p, off);
    float fg = 1.f / (1.f + expf(-(p + g_fmsc[b])));

    const float4* fr = (const float4*)(g_frout + b * HH);
    float4* op = (float4*)(out + row * HH);
#pragma unroll
    for (int i = 0; i < 6; i++) {
        float4 f = fr[lane + i * 32];
        float4 o;
        o.x = fg * f.x; o.y = fg * f.y; o.z = fg * f.z; o.w = fg * f.w;
        op[lane + i * 32] = o;
    }
}

// ================= launch =================
extern "C" void kernel_launch(void* const* d_in, const int* in_sizes, int n_in,
                              void* d_out, int out_size) {
    const float* text = (const float*)d_in[0];
    const float* img  = (const float*)d_in[1];
    const float* i1w  = (const float*)d_in[4];
    const float* a1w  = (const float*)d_in[5];
    const float* t2w  = (const float*)d_in[7];
    const float* a2w  = (const float*)d_in[10];
    const float* gtw  = (const float*)d_in[12];
    const float* gtb  = (const float*)d_in[13];
    const float* giw  = (const float*)d_in[14];
    const float* gib  = (const float*)d_in[15];
    const float* ggw  = (const float*)d_in[16];
    const float* ggb  = (const float*)d_in[17];
    const float* ftw  = (const float*)d_in[18];
    const float* fmw  = (const float*)d_in[19];
    const float* fmb  = (const float*)d_in[20];
    const float* fgw  = (const float*)d_in[21];
    const float* fgb  = (const float*)d_in[22];
    const float* frw  = (const float*)d_in[23];
    const float* frb  = (const float*)d_in[24];
    float* out = (float*)d_out;

    float* attI;  cudaGetSymbolAddress((void**)&attI,  g_attI);
    float* attT;  cudaGetSymbolAddress((void**)&attT,  g_attT);
    float* nI;    cudaGetSymbolAddress((void**)&nI,    g_nI);
    float* nT;    cudaGetSymbolAddress((void**)&nT,    g_nT);
    float* mm;    cudaGetSymbolAddress((void**)&mm,    g_mm);
    float* frout; cudaGetSymbolAddress((void**)&frout, g_frout);
    float* kscp;  cudaGetSymbolAddress((void**)&kscp,  g_ksc_part);
    float* iscp;  cudaGetSymbolAddress((void**)&iscp,  g_isc_part);
    __half *tF, *iF, *w2, *w1;
    cudaGetSymbolAddress((void**)&tF, g_tF);
    cudaGetSymbolAddress((void**)&iF, g_iF);
    cudaGetSymbolAddress((void**)&w2, g_w2);
    cudaGetSymbolAddress((void**)&w1, g_w1);

    cudaFuncSetAttribute(hmma_tanh_dot, cudaFuncAttributeMaxDynamicSharedMemorySize, HMMA_SMEM);

    prep_kernel<<<HH, 128>>>(ftw, fmw, fmb, fgw);

    // fp16 conversions / weight transposes
    cvt4<<<(MROWS_T * HH / 4 + 255) / 256, 256>>>(text, tF, MROWS_T * HH / 4);
    cvt4<<<(NROWS_I * HH / 4 + 255) / 256, 256>>>(img, iF, NROWS_I * HH / 4);
    {
        dim3 g(HH / 32, HH / 32, 2);
        tcvt<<<g, dim3(32, 8)>>>(t2w, i1w);
    }

    // i_sc partials (padded rows are zero -> guarded writes)
    {
        dim3 g(MROWS_I / 128, HH / 128);
        hmma_tanh_dot<<<g, 256, HMMA_SMEM>>>(iF, w1, a1w + HH, iscp, NROWS_I);
    }
    // k_sc partials
    {
        dim3 g(MROWS_T / 128, HH / 128);
        hmma_tanh_dot<<<g, 256, HMMA_SMEM>>>(tF, w2, a2w + HH, kscp, MROWS_T);
    }

    softmax_kernel<<<BB, 256>>>();

    {
        dim3 g(BB, NCB);
        attend_kernel<<<g, 128>>>(text, img);
    }
    {
        dim3 g(NCB, 2);
        small_gemm_tanh<<<g, 256>>>(attI, giw, gib, nI, attT, gtw, gtb, nT);
    }
    gate_mm_kernel<<<BB, 256>>>(ggw, ggb, fgb);
    {
        dim3 g(NCB, 1);
        small_gemm_tanh<<<g, 256>>>(mm, frw, frb, frout, mm, frw, frb, frout);
    }
    out_kernel<<<(BB * SS) / 8, 256>>>(text, out);
}

// round 8
// speedup vs baseline: 4.6431x; 1.0730x over previous
#include <cuda_runtime.h>
#include <cuda_fp16.h>
#include <stdint.h>

#define BB 32
#define SS 512
#define RR 49
#define HH 768
#define NCB 6              // 128-col blocks for small_gemm
#define NPART 24           // 32-col partial groups for the tensor GEMM
#define MROWS_T (BB*SS)    // 16384
#define NROWS_I (BB*RR)    // 1568
#define MROWS_I 1664       // padded to 13*128
#define TXB (MROWS_T/128)  // 128 text row-blocks

// ================= PTX helpers (sm_103-safe: ldmatrix / mma.sync / cp.async) =======
__device__ __forceinline__ uint32_t smem_u32(const void* p) {
    uint32_t a;
    asm("{ .reg .u64 t; cvta.to.shared.u64 t, %1; cvt.u32.u64 %0, t; }" : "=r"(a) : "l"(p));
    return a;
}
#define SMEM_SWIZZLE_128B(x) ((x) ^ (((x) >> 3) & 0x70))

__device__ __forceinline__ void cpa16(uint32_t s, const void* g) {
    asm volatile("cp.async.cg.shared.global [%0], [%1], 16;" :: "r"(s), "l"(g));
}
__device__ __forceinline__ void ldmx4(uint32_t* r, uint32_t addr) {
    asm volatile("ldmatrix.sync.aligned.m8n8.x4.shared.b16 {%0,%1,%2,%3}, [%4];"
                 : "=r"(r[0]), "=r"(r[1]), "=r"(r[2]), "=r"(r[3]) : "r"(addr));
}
__device__ __forceinline__ void mma16816(float* c, const uint32_t* a, uint32_t b0, uint32_t b1) {
    asm volatile(
        "mma.sync.aligned.m16n8k16.row.col.f32.f16.f16.f32 "
        "{%0,%1,%2,%3}, {%4,%5,%6,%7}, {%8,%9}, {%0,%1,%2,%3};"
        : "+f"(c[0]), "+f"(c[1]), "+f"(c[2]), "+f"(c[3])
        : "r"(a[0]), "r"(a[1]), "r"(a[2]), "r"(a[3]), "r"(b0), "r"(b1));
}
__device__ __forceinline__ float fast_tanh(float x) {
    const float e = __expf(2.f * x);
    return 1.f - __fdividef(2.f, e + 1.f);
}

// ================= scratch (device globals) =================
__device__ float g_ksc_part[NPART * MROWS_T];
__device__ float g_isc_part[NPART * NROWS_I];
__device__ __align__(16) float g_vft[HH];
__device__ __align__(16) float g_vfm[HH];
__device__ float g_fmc;
__device__ float g_fmsc[BB];
__device__ __align__(16) float g_frout[BB * HH];
__device__ float g_wimg[BB * RR];
__device__ float g_wtxt[BB * SS];
__device__ __align__(16) float g_attI[BB * HH];
__device__ __align__(16) float g_attT[BB * HH];
__device__ __align__(16) float g_nI[BB * HH];
__device__ __align__(16) float g_nT[BB * HH];
__device__ __align__(16) float g_mm[BB * HH];
// fp16 inputs + weights (transposed [n][k])
__device__ __align__(16) __half g_tF[MROWS_T * HH];
__device__ __align__(16) __half g_iF[MROWS_I * HH];   // pad rows stay zero
__device__ __align__(16) __half g_w2[HH * HH];
__device__ __align__(16) __half g_w1[HH * HH];

// ================= block reduce helpers =================
__device__ __forceinline__ float bsum(float v, float* sm) {
    int tid = threadIdx.x;
    sm[tid] = v; __syncthreads();
    for (int s = blockDim.x >> 1; s > 0; s >>= 1) {
        if (tid < s) sm[tid] += sm[tid + s];
        __syncthreads();
    }
    float r = sm[0]; __syncthreads();
    return r;
}
__device__ __forceinline__ float bmax(float v, float* sm) {
    int tid = threadIdx.x;
    sm[tid] = v; __syncthreads();
    for (int s = blockDim.x >> 1; s > 0; s >>= 1) {
        if (tid < s) sm[tid] = fmaxf(sm[tid], sm[tid + s]);
        __syncthreads();
    }
    float r = sm[0]; __syncthreads();
    return r;
}

// ================= input conversion: fp32 -> fp16 (text + img in one launch) ======
__global__ __launch_bounds__(256)
void cvt_all(const float* __restrict__ text, const float* __restrict__ img) {
    const int n4t = MROWS_T * HH / 4;
    const int n4i = NROWS_I * HH / 4;
    int i = blockIdx.x * 256 + threadIdx.x;
    const float* x;
    __half* o;
    int j;
    if (i < n4t) { x = text; o = g_tF; j = i; }
    else if (i < n4t + n4i) { x = img; o = g_iF; j = i - n4t; }
    else return;
    float4 v = ((const float4*)x)[j];
    union P { __half h[4]; uint2 u; } H;
    H.h[0] = __float2half(v.x); H.h[1] = __float2half(v.y);
    H.h[2] = __float2half(v.z); H.h[3] = __float2half(v.w);
    ((uint2*)o)[j] = H.u;
}

// transpose + convert weights: Ht[n][k] = fp16(W[k][n]); grid (24,24,2), block (32,8)
__global__ void tcvt(const float* __restrict__ W0, const float* __restrict__ W1) {
    __shared__ float t[32][33];
    const float* W = blockIdx.z ? W1 : W0;
    __half* Hi = blockIdx.z ? g_w1 : g_w2;
    const int kb = blockIdx.x * 32, nb = blockIdx.y * 32;
    const int tx = threadIdx.x, ty = threadIdx.y;
#pragma unroll
    for (int i = 0; i < 4; ++i)
        t[ty + 8 * i][tx] = W[(size_t)(kb + ty + 8 * i) * HH + nb + tx];
    __syncthreads();
#pragma unroll
    for (int i = 0; i < 4; ++i)
        Hi[(size_t)(nb + ty + 8 * i) * HH + kb + tx] = __float2half(t[tx][ty + 8 * i]);
}

// ================= prep: rank-1 collapses =================
__global__ void prep_kernel(const float* __restrict__ ftw, const float* __restrict__ fmw,
                            const float* __restrict__ fmb, const float* __restrict__ fgw) {
    __shared__ float red[128];
    const int k = blockIdx.x, tid = threadIdx.x;
    float s1 = 0.f, s2 = 0.f, s3 = 0.f;
    for (int h = tid; h < HH; h += 128) {
        float g1 = fgw[h], g2 = fgw[HH + h];
        s1 += ftw[k * HH + h] * g1;
        s2 += fmw[k * HH + h] * g2;
        if (k == 0) s3 += fmb[h] * g2;
    }
    float t1 = bsum(s1, red);
    float t2 = bsum(s2, red);
    if (tid == 0) { g_vft[k] = t1; g_vfm[k] = t2; }
    if (k == 0) {
        float t3 = bsum(s3, red);
        if (tid == 0) g_fmc = t3;
    }
}

// ================= single-pass fp16 HMMA GEMM + tanh + dot epilogue =================
// Merged launch: blockIdx.x < TXB -> text GEMM; else img GEMM.
// C[128x128] per CTA; K=768 in 12 chunks of 64; 3-stage pipeline, ONE sync/iter.
#define HMMA_SMEM (96 * 1024)

__device__ __forceinline__ void issue_chunk(
    const __half* __restrict__ Ap, const __half* __restrict__ Bp,
    int kt, uint32_t stageBase, int tid, int rowBase, int colBase) {
#pragma unroll
    for (int i = 0; i < 4; i++) {
        int u = tid + i * 256;                 // 1024 x 16B units
        cpa16(stageBase + SMEM_SWIZZLE_128B((uint32_t)u * 16u),
              Ap + (size_t)(rowBase + (u >> 3)) * HH + kt + (u & 7) * 8);
    }
#pragma unroll
    for (int i = 0; i < 4; i++) {
        int u = tid + i * 256;
        cpa16(stageBase + 16384u + SMEM_SWIZZLE_128B((uint32_t)u * 16u),
              Bp + (size_t)(colBase + (u >> 3)) * HH + kt + (u & 7) * 8);
    }
    asm volatile("cp.async.commit_group;");
}

__global__ __launch_bounds__(256, 2)
void hmma_tanh_dot(const __half* __restrict__ AT, const __half* __restrict__ AI,
                   const __half* __restrict__ WT, const __half* __restrict__ WI,
                   const float* __restrict__ avT, const float* __restrict__ avI,
                   float* __restrict__ outT, float* __restrict__ outI) {
    extern __shared__ __align__(1024) char smem[];
    const uint32_t sb = smem_u32(smem);
    const int tid = threadIdx.x;
    const int wid = tid >> 5, lane = tid & 31;
    const int warpm = wid & 1, warpn = wid >> 1;   // 2 x 4 warp grid, warp tile 64x32
    const int bx = blockIdx.x;
    const bool isT = bx < TXB;
    const __half* A = isT ? AT : AI;
    const __half* W = isT ? WT : WI;
    const float* av = isT ? avT : avI;
    float* outPart = isT ? outT : outI;
    const int nrows = isT ? MROWS_T : NROWS_I;
    const int rowBase = (isT ? bx : bx - TXB) * 128;
    const int colBase = blockIdx.y * 128;

    float acc[4][4][4];
#pragma unroll
    for (int i = 0; i < 4; i++)
#pragma unroll
        for (int j = 0; j < 4; j++)
#pragma unroll
            for (int q = 0; q < 4; q++) acc[i][j][q] = 0.f;

    issue_chunk(A, W, 0, sb, tid, rowBase, colBase);
    issue_chunk(A, W, 64, sb + 32768u, tid, rowBase, colBase);

    for (int it = 0; it < 12; ++it) {
        if (it < 11) asm volatile("cp.async.wait_group 1;");
        else         asm volatile("cp.async.wait_group 0;");
        __syncthreads();     // chunk `it` visible to all; compute of it-1 done by all
        if (it < 10)         // safe: targets buffer (it+2)%3 == (it-1)%3, already consumed
            issue_chunk(A, W, (it + 2) * 64, sb + (uint32_t)((it + 2) % 3) * 32768u,
                        tid, rowBase, colBase);

        const uint32_t abase = sb + (uint32_t)(it % 3) * 32768u;
        const uint32_t bbase = abase + 16384u;
#pragma unroll
        for (int ks = 0; ks < 4; ++ks) {
            uint32_t bf[2][4];
#pragma unroll
            for (int g = 0; g < 2; ++g) {
                const int n = warpn * 32 + g * 16 + (lane & 7) + ((lane >> 4) << 3);
                const int kb = ks * 32 + ((lane >> 3) & 1) * 16;
                ldmx4(bf[g], bbase + SMEM_SWIZZLE_128B((uint32_t)(n * 128 + kb)));
            }
#pragma unroll
            for (int mt = 0; mt < 4; ++mt) {
                uint32_t a[4];
                const int r = warpm * 64 + mt * 16 + (lane & 15);
                const int kb = ks * 32 + ((lane >> 4) << 4);
                ldmx4(a, abase + SMEM_SWIZZLE_128B((uint32_t)(r * 128 + kb)));
#pragma unroll
                for (int nt = 0; nt < 4; ++nt)
                    mma16816(acc[mt][nt], a, bf[nt >> 1][(nt & 1) * 2],
                             bf[nt >> 1][(nt & 1) * 2 + 1]);
            }
        }
    }

    // ---- epilogue: tanh * av, reduce over this warp's 32 cols, write row partials ----
    const float* avp = av + colBase + warpn * 32;
    float avv[4][2];
#pragma unroll
    for (int nt = 0; nt < 4; ++nt) {
        avv[nt][0] = avp[nt * 8 + (lane & 3) * 2];
        avv[nt][1] = avp[nt * 8 + (lane & 3) * 2 + 1];
    }
    const int gcol = blockIdx.y * 4 + warpn;
#pragma unroll
    for (int mt = 0; mt < 4; ++mt) {
        float s0 = 0.f, s1 = 0.f;
#pragma unroll
        for (int nt = 0; nt < 4; ++nt) {
            s0 += fast_tanh(acc[mt][nt][0]) * avv[nt][0] + fast_tanh(acc[mt][nt][1]) * avv[nt][1];
            s1 += fast_tanh(acc[mt][nt][2]) * avv[nt][0] + fast_tanh(acc[mt][nt][3]) * avv[nt][1];
        }
        s0 += __shfl_xor_sync(0xffffffffu, s0, 1);
        s0 += __shfl_xor_sync(0xffffffffu, s0, 2);
        s1 += __shfl_xor_sync(0xffffffffu, s1, 1);
        s1 += __shfl_xor_sync(0xffffffffu, s1, 2);
        if ((lane & 3) == 0) {
            const int r0 = rowBase + warpm * 64 + mt * 16 + (lane >> 2);
            if (r0 < nrows) outPart[gcol * nrows + r0] = s0;
            if (r0 + 8 < nrows) outPart[gcol * nrows + r0 + 8] = s1;
        }
    }
}

// ================= softmaxes =================
__global__ void softmax_kernel() {
    __shared__ float red[256];
    __shared__ float w[SS];
    const int b = blockIdx.x, tid = threadIdx.x;

    float s0 = -1e30f;
    if (tid < RR) {
        float s = 0.f;
#pragma unroll
        for (int c = 0; c < NPART; c++) s += g_isc_part[c * NROWS_I + b * RR + tid];
        w[tid] = s; s0 = s;
    }
    float mx = bmax(s0, red);
    float ex = 0.f;
    if (tid < RR) ex = expf(w[tid] - mx);
    float tot = bsum(ex, red);
    if (tid < RR) g_wimg[b * RR + tid] = ex / tot;

    float mx2 = -1e30f;
    for (int j = tid; j < SS; j += 256) {
        float s = 0.f;
#pragma unroll
        for (int c = 0; c < NPART; c++) s += g_ksc_part[c * MROWS_T + b * SS + j];
        w[j] = s; mx2 = fmaxf(mx2, s);
    }
    mx2 = bmax(mx2, red);
    float es = 0.f;
    for (int j = tid; j < SS; j += 256) { float e = expf(w[j] - mx2); w[j] = e; es += e; }
    tot = bsum(es, red);
    float inv = 1.f / tot;
    for (int j = tid; j < SS; j += 256) g_wtxt[b * SS + j] = w[j] * inv;
}

// ================= attended vectors: fp16 text, half2 cols; grid (B,3), block 128 ==
__global__ __launch_bounds__(128)
void attend_kernel(const float* __restrict__ img) {
    __shared__ float wt[SS];
    __shared__ float wi[RR];
    const int b = blockIdx.x, tid = threadIdx.x;
    const int c = blockIdx.y * 128 + tid;     // half2 column index, 0..383

    for (int j = tid; j < SS; j += 128) wt[j] = g_wtxt[b * SS + j];
    if (tid < RR) wi[tid] = g_wimg[b * RR + tid];
    __syncthreads();

    // att_text from fp16 text
    {
        const __half2* tp = (const __half2*)g_tF + (size_t)b * SS * (HH / 2) + c;
        float2 a0 = {0.f, 0.f}, a1 = {0.f, 0.f};
#pragma unroll 2
        for (int j = 0; j < SS; j += 2) {
            float2 v0 = __half22float2(tp[(size_t)(j + 0) * (HH / 2)]);
            float2 v1 = __half22float2(tp[(size_t)(j + 1) * (HH / 2)]);
            a0.x += wt[j] * v0.x;     a0.y += wt[j] * v0.y;
            a1.x += wt[j + 1] * v1.x; a1.y += wt[j + 1] * v1.y;
        }
        float2 o; o.x = a0.x + a1.x; o.y = a0.y + a1.y;
        ((float2*)(g_attT + b * HH))[c] = o;
    }
    // att_img from fp32 img
    {
        const float2* ip = (const float2*)(img + (size_t)b * RR * HH) + c;
        float2 a = {0.f, 0.f};
#pragma unroll
        for (int r = 0; r < RR; r++) {
            float2 v = ip[(size_t)r * (HH / 2)];
            a.x += wi[r] * v.x; a.y += wi[r] * v.y;
        }
        ((float2*)(g_attI + b * HH))[c] = a;
    }
}

// ================= small GEMM: C[32,768] = tanh(A @ W + bias) =================
__global__ __launch_bounds__(256)
void small_gemm_tanh(const float* __restrict__ A0, const float* __restrict__ W0,
                     const float* __restrict__ b0, float* __restrict__ C0,
                     const float* __restrict__ A1, const float* __restrict__ W1,
                     const float* __restrict__ b1, float* __restrict__ C1) {
    const float* A = blockIdx.y ? A1 : A0;
    const float* W = blockIdx.y ? W1 : W0;
    const float* bias = blockIdx.y ? b1 : b0;
    float* C = blockIdx.y ? C1 : C0;

    __shared__ __align__(16) float As[32][36];
    __shared__ __align__(16) float Ws[32][128];
    const int tid = threadIdx.x;
    const int colBase = blockIdx.x * 128;
    const int tx = tid & 31;
    const int ty = tid >> 5;

    float acc[4][4];
#pragma unroll
    for (int i = 0; i < 4; i++)
#pragma unroll
        for (int j = 0; j < 4; j++) acc[i][j] = 0.f;

    for (int kt = 0; kt < HH; kt += 32) {
        {
            int r = tid >> 3;
            int kg = (tid & 7) << 2;
            float4 v = *(const float4*)(A + r * HH + kt + kg);
            As[kg + 0][r] = v.x; As[kg + 1][r] = v.y;
            As[kg + 2][r] = v.z; As[kg + 3][r] = v.w;
        }
#pragma unroll
        for (int i = 0; i < 4; i++) {
            int idx = tid + i * 256;
            int kk = idx >> 5;
            int ng = (idx & 31) << 2;
            *(float4*)&Ws[kk][ng] = *(const float4*)(W + (kt + kk) * HH + colBase + ng);
        }
        __syncthreads();
#pragma unroll
        for (int k = 0; k < 32; k++) {
            float4 av4 = *(const float4*)&As[k][ty * 4];
            float4 w = *(const float4*)&Ws[k][tx * 4];
            float a[4] = {av4.x, av4.y, av4.z, av4.w};
#pragma unroll
            for (int i = 0; i < 4; i++) {
                acc[i][0] = fmaf(a[i], w.x, acc[i][0]);
                acc[i][1] = fmaf(a[i], w.y, acc[i][1]);
                acc[i][2] = fmaf(a[i], w.z, acc[i][2]);
                acc[i][3] = fmaf(a[i], w.w, acc[i][3]);
            }
        }
        __syncthreads();
    }

    int col = colBase + tx * 4;
    float4 bv = *(const float4*)(bias + col);
#pragma unroll
    for (int i = 0; i < 4; i++) {
        int row = ty * 4 + i;
        float4 o;
        o.x = tanhf(acc[i][0] + bv.x);
        o.y = tanhf(acc[i][1] + bv.y);
        o.z = tanhf(acc[i][2] + bv.z);
        o.w = tanhf(acc[i][3] + bv.w);
        *(float4*)(C + row * HH + col) = o;
    }
}

// ================= gate + multimodal + fm score =================
__global__ void gate_mm_kernel(const float* __restrict__ ggw, const float* __restrict__ ggb,
                               const float* __restrict__ fgb) {
    __shared__ float red[256];
    const int b = blockIdx.x, tid = threadIdx.x;

    float gp = 0.f;
    for (int h = tid; h < HH; h += 256)
        gp += g_nI[b * HH + h] * ggw[h] + g_nT[b * HH + h] * ggw[HH + h];
    float gs = bsum(gp, red);
    float gate = 1.f / (1.f + expf(-(gs + ggb[0])));

    float fmp = 0.f;
    for (int h = tid; h < HH; h += 256) {
        float v = gate * g_nI[b * HH + h] + (1.f - gate) * g_nT[b * HH + h];
        g_mm[b * HH + h] = v;
        fmp += v * g_vfm[h];
    }
    float fsum = bsum(fmp, red);
    if (tid == 0) g_fmsc[b] = fsum + g_fmc + fgb[0];
}

// ================= output: warp per row, fp16 text for the gate dot =================
__global__ __launch_bounds__(256)
void out_kernel(float* __restrict__ out) {
    const int warp = threadIdx.x >> 5;
    const int lane = threadIdx.x & 31;
    const int row = blockIdx.x * 8 + warp;
    const int b = row >> 9;

    const __half2* tv = (const __half2*)g_tF + (size_t)row * (HH / 2);
    const float2* vv = (const float2*)g_vft;
    float p = 0.f;
#pragma unroll
    for (int i = 0; i < 12; i++) {
        float2 t = __half22float2(tv[lane + i * 32]);
        float2 v = vv[lane + i * 32];
        p += t.x * v.x + t.y * v.y;
    }
#pragma unroll
    for (int off = 16; off > 0; off >>= 1) p += __shfl_xor_sync(0xffffffffu, p, off);
    float fg = 1.f / (1.f + expf(-(p + g_fmsc[b])));

    const float4* fr = (const float4*)(g_frout + b * HH);
    float4* op = (float4*)(out + (size_t)row * HH);
#pragma unroll
    for (int i = 0; i < 6; i++) {
        float4 f = fr[lane + i * 32];
        float4 o;
        o.x = fg * f.x; o.y = fg * f.y; o.z = fg * f.z; o.w = fg * f.w;
        op[lane + i * 32] = o;
    }
}

// ================= launch =================
extern "C" void kernel_launch(void* const* d_in, const int* in_sizes, int n_in,
                              void* d_out, int out_size) {
    const float* text = (const float*)d_in[0];
    const float* img  = (const float*)d_in[1];
    const float* i1w  = (const float*)d_in[4];
    const float* a1w  = (const float*)d_in[5];
    const float* t2w  = (const float*)d_in[7];
    const float* a2w  = (const float*)d_in[10];
    const float* gtw  = (const float*)d_in[12];
    const float* gtb  = (const float*)d_in[13];
    const float* giw  = (const float*)d_in[14];
    const float* gib  = (const float*)d_in[15];
    const float* ggw  = (const float*)d_in[16];
    const float* ggb  = (const float*)d_in[17];
    const float* ftw  = (const float*)d_in[18];
    const float* fmw  = (const float*)d_in[19];
    const float* fmb  = (const float*)d_in[20];
    const float* fgw  = (const float*)d_in[21];
    const float* fgb  = (const float*)d_in[22];
    const float* frw  = (const float*)d_in[23];
    const float* frb  = (const float*)d_in[24];
    float* out = (float*)d_out;

    float* attI;  cudaGetSymbolAddress((void**)&attI,  g_attI);
    float* attT;  cudaGetSymbolAddress((void**)&attT,  g_attT);
    float* nI;    cudaGetSymbolAddress((void**)&nI,    g_nI);
    float* nT;    cudaGetSymbolAddress((void**)&nT,    g_nT);
    float* mm;    cudaGetSymbolAddress((void**)&mm,    g_mm);
    float* frout; cudaGetSymbolAddress((void**)&frout, g_frout);
    float* kscp;  cudaGetSymbolAddress((void**)&kscp,  g_ksc_part);
    float* iscp;  cudaGetSymbolAddress((void**)&iscp,  g_isc_part);
    __half *tF, *iF, *w2, *w1;
    cudaGetSymbolAddress((void**)&tF, g_tF);
    cudaGetSymbolAddress((void**)&iF, g_iF);
    cudaGetSymbolAddress((void**)&w2, g_w2);
    cudaGetSymbolAddress((void**)&w1, g_w1);

    cudaFuncSetAttribute(hmma_tanh_dot, cudaFuncAttributeMaxDynamicSharedMemorySize, HMMA_SMEM);

    prep_kernel<<<HH, 128>>>(ftw, fmw, fmb, fgw);

    // fp16 conversions (text + img) and weight transposes
    {
        int n4 = (MROWS_T + NROWS_I) * HH / 4;
        cvt_all<<<(n4 + 255) / 256, 256>>>(text, img);
    }
    {
        dim3 g(HH / 32, HH / 32, 2);
        tcvt<<<g, dim3(32, 8)>>>(t2w, i1w);
    }

    // merged text + img GEMM partials
    {
        dim3 g(TXB + MROWS_I / 128, HH / 128);
        hmma_tanh_dot<<<g, 256, HMMA_SMEM>>>(tF, iF, w2, w1, a2w + HH, a1w + HH, kscp, iscp);
    }

    softmax_kernel<<<BB, 256>>>();

    {
        dim3 g(BB, 3);
        attend_kernel<<<g, 128>>>(img);
    }
    {
        dim3 g(NCB, 2);
        small_gemm_tanh<<<g, 256>>>(attI, giw, gib, nI, attT, gtw, gtb, nT);
    }
    gate_mm_kernel<<<BB, 256>>>(ggw, ggb, fgb);
    {
        dim3 g(NCB, 1);
        small_gemm_tanh<<<g, 256>>>(mm, frw, frb, frout, mm, frw, frb, frout);
    }
    out_kernel<<<(BB * SS) / 8, 256>>>(out);
}